// round 1
// baseline (speedup 1.0000x reference)
#include <cuda_runtime.h>
#include <stdint.h>

#define GN 4096
#define GH 8
#define FCAT 512        // H*HID = 8*64, also F_IN
#define HIDF 64
#define ADJW (GN/32)    // 128 words per row

// ---------------- scratch (device globals, no allocations) ----------------
__device__ uint32_t g_adjbits[GN * ADJW];     // 2 MB packed adjacency
__device__ float    g_wh1[GN * FCAT];         // layer-1 wh, [i][h*64+f]
__device__ float    g_s1[GH * GN];            // [h][i]
__device__ float    g_s2[GH * GN];
__device__ float    g_gmax[GH];
__device__ float    g_hbuf[GN * FCAT];        // layer-1 output (post-ELU concat)
__device__ float    g_wh2[GN * HIDF];
__device__ float    g_s21[GN];
__device__ float    g_s22[GN];
__device__ float    g_gmax2[1];

// ---------------- pack adjacency int32 -> bitmask ----------------
__global__ void pack_adj_kernel(const int* __restrict__ adj,
                                uint32_t* __restrict__ bits) {
    int t = blockIdx.x * 256 + threadIdx.x;           // linear over N*N
    uint32_t b = __ballot_sync(0xffffffffu, adj[t] > 0);
    if ((threadIdx.x & 31) == 0) bits[t >> 5] = b;
}

// ---------------- C[m][n] = sum_k A[m*K+k] * B[n*K+k] (A row-major, B row-major "NT") ----
__global__ void gemm_nt_kernel(const float* __restrict__ A,
                               const float* __restrict__ B,
                               float* __restrict__ C,
                               int M, int Ncols, int K) {
    __shared__ float As[16][68];  // [k][m]
    __shared__ float Bs[16][68];  // [k][n]
    int t  = threadIdx.x;
    int tx = t & 15, ty = t >> 4;
    int m0 = blockIdx.y * 64;
    int n0 = blockIdx.x * 64;
    int row = t >> 2;             // 0..63
    int kq  = (t & 3) * 4;        // 0,4,8,12
    float acc[4][4];
#pragma unroll
    for (int i = 0; i < 4; ++i)
#pragma unroll
        for (int j = 0; j < 4; ++j) acc[i][j] = 0.f;

    for (int k0 = 0; k0 < K; k0 += 16) {
        float4 av = *(const float4*)&A[(size_t)(m0 + row) * K + k0 + kq];
        float4 bv = *(const float4*)&B[(size_t)(n0 + row) * K + k0 + kq];
        As[kq + 0][row] = av.x; As[kq + 1][row] = av.y;
        As[kq + 2][row] = av.z; As[kq + 3][row] = av.w;
        Bs[kq + 0][row] = bv.x; Bs[kq + 1][row] = bv.y;
        Bs[kq + 2][row] = bv.z; Bs[kq + 3][row] = bv.w;
        __syncthreads();
#pragma unroll
        for (int k = 0; k < 16; ++k) {
            float4 a = *(const float4*)&As[k][ty * 4];
            float4 b = *(const float4*)&Bs[k][tx * 4];
            acc[0][0] += a.x * b.x; acc[0][1] += a.x * b.y; acc[0][2] += a.x * b.z; acc[0][3] += a.x * b.w;
            acc[1][0] += a.y * b.x; acc[1][1] += a.y * b.y; acc[1][2] += a.y * b.z; acc[1][3] += a.y * b.w;
            acc[2][0] += a.z * b.x; acc[2][1] += a.z * b.y; acc[2][2] += a.z * b.z; acc[2][3] += a.z * b.w;
            acc[3][0] += a.w * b.x; acc[3][1] += a.w * b.y; acc[3][2] += a.w * b.z; acc[3][3] += a.w * b.w;
        }
        __syncthreads();
    }
#pragma unroll
    for (int i = 0; i < 4; ++i) {
        float4 v = make_float4(acc[i][0], acc[i][1], acc[i][2], acc[i][3]);
        *(float4*)&C[(size_t)(m0 + ty * 4 + i) * Ncols + n0 + tx * 4] = v;
    }
}

// ---------------- s1[h][i] = wh[i, h*64:]·a1[h], s2 likewise (warp per (i,h)) ----
__global__ void scores_kernel(const float* __restrict__ wh, int stride, int nH,
                              const float* __restrict__ a1, const float* __restrict__ a2,
                              float* __restrict__ s1, float* __restrict__ s2) {
    int w    = blockIdx.x * 8 + (threadIdx.x >> 5);
    int lane = threadIdx.x & 31;
    int i = w / nH, h = w % nH;
    const float* base = wh + (size_t)i * stride + h * 64;
    float v0 = base[lane], v1 = base[lane + 32];
    float p1 = v0 * a1[h * 64 + lane] + v1 * a1[h * 64 + lane + 32];
    float p2 = v0 * a2[h * 64 + lane] + v1 * a2[h * 64 + lane + 32];
#pragma unroll
    for (int o = 16; o; o >>= 1) {
        p1 += __shfl_down_sync(0xffffffffu, p1, o);
        p2 += __shfl_down_sync(0xffffffffu, p2, o);
    }
    if (lane == 0) { s1[h * GN + i] = p1; s2[h * GN + i] = p2; }
}

// ---------------- per-head global max of s2 ----------------
__global__ void rowmax_kernel(const float* __restrict__ s2, float* __restrict__ gmax) {
    int h = blockIdx.x;
    __shared__ float sm[256];
    float m = -1e30f;
    for (int i = threadIdx.x; i < GN; i += 256) m = fmaxf(m, s2[h * GN + i]);
    sm[threadIdx.x] = m;
    __syncthreads();
    for (int s = 128; s; s >>= 1) {
        if (threadIdx.x < s) sm[threadIdx.x] = fmaxf(sm[threadIdx.x], sm[threadIdx.x + s]);
        __syncthreads();
    }
    if (threadIdx.x == 0) gmax[h] = sm[0];
}

// ---------------- fused masked softmax + att@wh (single pass, fixed shift) ----
// block: 256 threads = 32 rows x 8 f-groups; tile over j in chunks of 64.
__global__ void attn_kernel(const float* __restrict__ wh, int whStride,
                            const float* __restrict__ s1, const float* __restrict__ s2,
                            const float* __restrict__ gmaxp,
                            const uint32_t* __restrict__ adjbits,
                            float* __restrict__ out, int outStride, int applyElu) {
    __shared__ float    whs[64][64];
    __shared__ float    ps[32][65];     // padded: avoid 4-way conflicts on [i][j]
    __shared__ float    s2s[64];
    __shared__ uint32_t ab[32][2];

    int t  = threadIdx.x;
    int i  = t >> 3;      // 0..31 (row within block)
    int fg = t & 7;       // 0..7  (feature group of 8)
    int i0 = blockIdx.x * 32;
    int h  = blockIdx.y;

    float s1i = s1[h * GN + i0 + i];
    float gm  = gmaxp[h];
    float me  = s1i + gm;
    float m   = me > 0.f ? me : 0.2f * me;   // leaky is monotone -> valid upper bound

    float acc[8];
#pragma unroll
    for (int q = 0; q < 8; ++q) acc[q] = 0.f;
    float den = 0.f;

    const float* whB = wh + h * 64;
    const float* s2B = s2 + h * GN;

    for (int j0 = 0; j0 < GN; j0 += 64) {
        // load wh tile [64 j][64 f]
#pragma unroll
        for (int it = 0; it < 4; ++it) {
            int idx = it * 256 + t;
            int jr  = idx >> 4;
            int f4  = (idx & 15) << 2;
            *(float4*)&whs[jr][f4] =
                *(const float4*)&whB[(size_t)(j0 + jr) * whStride + f4];
        }
        if (t < 64) {
            s2s[t] = s2B[j0 + t];
        } else if (t < 128) {
            int u = t - 64;
            ab[u >> 1][u & 1] =
                adjbits[(size_t)(i0 + (u >> 1)) * ADJW + (j0 >> 5) + (u & 1)];
        }
        __syncthreads();

        // phase 1: p for (i, j = fg*8 .. fg*8+7)
        uint32_t b0 = ab[i][0], b1 = ab[i][1];
        int jb = fg * 8;
#pragma unroll
        for (int q = 0; q < 8; ++q) {
            int j = jb + q;
            float e  = s1i + s2s[j];
            float le = e > 0.f ? e : 0.2f * e;
            uint32_t w = (j < 32) ? b0 : b1;
            ps[i][j] = ((w >> (j & 31)) & 1u) ? __expf(le - m) : 0.f;
        }
        __syncthreads();

        // phase 2: acc += p * wh
#pragma unroll 16
        for (int j = 0; j < 64; ++j) {
            float pj = ps[i][j];
            den += pj;
            float4 a = *(const float4*)&whs[j][fg * 8];
            float4 b = *(const float4*)&whs[j][fg * 8 + 4];
            acc[0] += pj * a.x; acc[1] += pj * a.y; acc[2] += pj * a.z; acc[3] += pj * a.w;
            acc[4] += pj * b.x; acc[5] += pj * b.y; acc[6] += pj * b.z; acc[7] += pj * b.w;
        }
        __syncthreads();
    }

    float inv = 1.f / den;
    float r[8];
#pragma unroll
    for (int q = 0; q < 8; ++q) {
        float v = acc[q] * inv;
        if (applyElu) v = v > 0.f ? v : (__expf(v) - 1.f);
        r[q] = v;
    }
    float* op = out + (size_t)(i0 + i) * outStride + h * 64 + fg * 8;
    *(float4*)op       = make_float4(r[0], r[1], r[2], r[3]);
    *(float4*)(op + 4) = make_float4(r[4], r[5], r[6], r[7]);
}

// ---------------- final: ELU then log_softmax per row of 64, in place ----
__global__ void elu_lsm_kernel(float* __restrict__ out) {
    int row  = blockIdx.x * 8 + (threadIdx.x >> 5);
    int lane = threadIdx.x & 31;
    float* p = out + (size_t)row * 64;
    float v0 = p[lane], v1 = p[lane + 32];
    v0 = v0 > 0.f ? v0 : (__expf(v0) - 1.f);
    v1 = v1 > 0.f ? v1 : (__expf(v1) - 1.f);
    float mx = fmaxf(v0, v1);
#pragma unroll
    for (int o = 16; o; o >>= 1) mx = fmaxf(mx, __shfl_xor_sync(0xffffffffu, mx, o));
    float s = __expf(v0 - mx) + __expf(v1 - mx);
#pragma unroll
    for (int o = 16; o; o >>= 1) s += __shfl_xor_sync(0xffffffffu, s, o);
    float l = mx + __logf(s);
    p[lane]      = v0 - l;
    p[lane + 32] = v1 - l;
}

// ---------------- launch ----------------
extern "C" void kernel_launch(void* const* d_in, const int* in_sizes, int n_in,
                              void* d_out, int out_size) {
    const float* x   = (const float*)d_in[0];
    const int*   adj = (const int*)d_in[1];
    const float* W   = (const float*)d_in[2];   // [8,64,512] -> flat [512,512]
    const float* a1  = (const float*)d_in[3];   // [8,64]
    const float* a2  = (const float*)d_in[4];
    const float* W2  = (const float*)d_in[5];   // [64,512]
    const float* a21 = (const float*)d_in[6];   // [64]
    const float* a22 = (const float*)d_in[7];
    float* out = (float*)d_out;

    uint32_t* adjbits; float *wh1, *s1, *s2, *gm, *hbuf, *wh2, *s21, *s22, *gm2;
    cudaGetSymbolAddress((void**)&adjbits, g_adjbits);
    cudaGetSymbolAddress((void**)&wh1,  g_wh1);
    cudaGetSymbolAddress((void**)&s1,   g_s1);
    cudaGetSymbolAddress((void**)&s2,   g_s2);
    cudaGetSymbolAddress((void**)&gm,   g_gmax);
    cudaGetSymbolAddress((void**)&hbuf, g_hbuf);
    cudaGetSymbolAddress((void**)&wh2,  g_wh2);
    cudaGetSymbolAddress((void**)&s21,  g_s21);
    cudaGetSymbolAddress((void**)&s22,  g_s22);
    cudaGetSymbolAddress((void**)&gm2,  g_gmax2);

    // 1. pack adjacency to bitmask (67 MB read once)
    pack_adj_kernel<<<(GN * GN) / 256, 256>>>(adj, adjbits);
    // 2. layer-1 feature GEMM: wh1[4096,512] = x @ Wcat^T
    gemm_nt_kernel<<<dim3(FCAT / 64, GN / 64), 256>>>(x, W, wh1, GN, FCAT, FCAT);
    // 3. scores per head
    scores_kernel<<<(GN * GH) / 8, 256>>>(wh1, FCAT, GH, a1, a2, s1, s2);
    rowmax_kernel<<<GH, 256>>>(s2, gm);
    // 4. fused masked softmax + att@wh + ELU, all 8 heads
    attn_kernel<<<dim3(GN / 32, GH), 256>>>(wh1, FCAT, s1, s2, gm, adjbits,
                                            hbuf, FCAT, 1);
    // 5. layer-2 GEMM: wh2[4096,64] = h @ W2^T
    gemm_nt_kernel<<<dim3(1, GN / 64), 256>>>(hbuf, W2, wh2, GN, HIDF, FCAT);
    // 6. layer-2 scores + attention (raw att@wh into d_out)
    scores_kernel<<<GN / 8, 256>>>(wh2, HIDF, 1, a21, a22, s21, s22);
    rowmax_kernel<<<1, 256>>>(s22, gm2);
    attn_kernel<<<dim3(GN / 32, 1), 256>>>(wh2, HIDF, s21, s22, gm2, adjbits,
                                           out, HIDF, 0);
    // 7. ELU + log_softmax in place
    elu_lsm_kernel<<<GN / 8, 256>>>(out);
}

// round 2
// speedup vs baseline: 2.9687x; 2.9687x over previous
#include <cuda_runtime.h>
#include <cuda_bf16.h>
#include <stdint.h>

#define GN 4096
#define GH 8
#define FCAT 512        // H*HID = 8*64, also F_IN
#define HIDF 64
#define ADJW (GN/32)    // 128 words per row

// ---------------- scratch (device globals, no allocations) ----------------
__device__ uint32_t      g_adjbits[GN * ADJW];     // 2 MB packed adjacency
__device__ float         g_wh1[GN * FCAT];         // layer-1 wh fp32 [i][h*64+f]
__device__ __nv_bfloat16 g_whTb[FCAT * GN];        // transposed bf16 [h*64+f][j]
__device__ float         g_s1[GH * GN];
__device__ float         g_s2[GH * GN];
__device__ float         g_gmax[GH];
__device__ float         g_hbuf[GN * FCAT];        // layer-1 output (post-ELU concat)
__device__ float         g_wh2[GN * HIDF];
__device__ __nv_bfloat16 g_whT2b[HIDF * GN];
__device__ float         g_s21[GN];
__device__ float         g_s22[GN];
__device__ float         g_gmax2[1];

// ---------------- pack adjacency int32 -> bitmask ----------------
__global__ void pack_adj_kernel(const int* __restrict__ adj,
                                uint32_t* __restrict__ bits) {
    int t = blockIdx.x * 256 + threadIdx.x;
    uint32_t b = __ballot_sync(0xffffffffu, adj[t] > 0);
    if ((threadIdx.x & 31) == 0) bits[t >> 5] = b;
}

// ---------------- C[m][n] = sum_k A[m*K+k]*B[n*K+k] ----------------
__global__ void gemm_nt_kernel(const float* __restrict__ A,
                               const float* __restrict__ B,
                               float* __restrict__ C,
                               int M, int Ncols, int K) {
    __shared__ float As[16][68];
    __shared__ float Bs[16][68];
    int t  = threadIdx.x;
    int tx = t & 15, ty = t >> 4;
    int m0 = blockIdx.y * 64;
    int n0 = blockIdx.x * 64;
    int row = t >> 2;
    int kq  = (t & 3) * 4;
    float acc[4][4];
#pragma unroll
    for (int i = 0; i < 4; ++i)
#pragma unroll
        for (int j = 0; j < 4; ++j) acc[i][j] = 0.f;

    for (int k0 = 0; k0 < K; k0 += 16) {
        float4 av = *(const float4*)&A[(size_t)(m0 + row) * K + k0 + kq];
        float4 bv = *(const float4*)&B[(size_t)(n0 + row) * K + k0 + kq];
        As[kq + 0][row] = av.x; As[kq + 1][row] = av.y;
        As[kq + 2][row] = av.z; As[kq + 3][row] = av.w;
        Bs[kq + 0][row] = bv.x; Bs[kq + 1][row] = bv.y;
        Bs[kq + 2][row] = bv.z; Bs[kq + 3][row] = bv.w;
        __syncthreads();
#pragma unroll
        for (int k = 0; k < 16; ++k) {
            float4 a = *(const float4*)&As[k][ty * 4];
            float4 b = *(const float4*)&Bs[k][tx * 4];
            acc[0][0] += a.x * b.x; acc[0][1] += a.x * b.y; acc[0][2] += a.x * b.z; acc[0][3] += a.x * b.w;
            acc[1][0] += a.y * b.x; acc[1][1] += a.y * b.y; acc[1][2] += a.y * b.z; acc[1][3] += a.y * b.w;
            acc[2][0] += a.z * b.x; acc[2][1] += a.z * b.y; acc[2][2] += a.z * b.z; acc[2][3] += a.z * b.w;
            acc[3][0] += a.w * b.x; acc[3][1] += a.w * b.y; acc[3][2] += a.w * b.z; acc[3][3] += a.w * b.w;
        }
        __syncthreads();
    }
#pragma unroll
    for (int i = 0; i < 4; ++i) {
        float4 v = make_float4(acc[i][0], acc[i][1], acc[i][2], acc[i][3]);
        *(float4*)&C[(size_t)(m0 + ty * 4 + i) * Ncols + n0 + tx * 4] = v;
    }
}

// ---------------- scores ----------------
__global__ void scores_kernel(const float* __restrict__ wh, int stride, int nH,
                              const float* __restrict__ a1, const float* __restrict__ a2,
                              float* __restrict__ s1, float* __restrict__ s2) {
    int w    = blockIdx.x * 8 + (threadIdx.x >> 5);
    int lane = threadIdx.x & 31;
    int i = w / nH, h = w % nH;
    const float* base = wh + (size_t)i * stride + h * 64;
    float v0 = base[lane], v1 = base[lane + 32];
    float p1 = v0 * a1[h * 64 + lane] + v1 * a1[h * 64 + lane + 32];
    float p2 = v0 * a2[h * 64 + lane] + v1 * a2[h * 64 + lane + 32];
#pragma unroll
    for (int o = 16; o; o >>= 1) {
        p1 += __shfl_down_sync(0xffffffffu, p1, o);
        p2 += __shfl_down_sync(0xffffffffu, p2, o);
    }
    if (lane == 0) { s1[h * GN + i] = p1; s2[h * GN + i] = p2; }
}

// ---------------- per-head global max of s2 ----------------
__global__ void rowmax_kernel(const float* __restrict__ s2, float* __restrict__ gmax) {
    int h = blockIdx.x;
    __shared__ float sm[256];
    float m = -1e30f;
    for (int i = threadIdx.x; i < GN; i += 256) m = fmaxf(m, s2[h * GN + i]);
    sm[threadIdx.x] = m;
    __syncthreads();
    for (int s = 128; s; s >>= 1) {
        if (threadIdx.x < s) sm[threadIdx.x] = fmaxf(sm[threadIdx.x], sm[threadIdx.x + s]);
        __syncthreads();
    }
    if (threadIdx.x == 0) gmax[h] = sm[0];
}

// ---------------- fp32 [GN][C] -> bf16 transposed [C][GN] ----------------
__global__ void cvt_t_kernel(const float* __restrict__ in,
                             __nv_bfloat16* __restrict__ out, int C) {
    int id = blockIdx.x * 256 + threadIdx.x;      // over C * 2048
    int c  = id >> 11;
    int jp = (id & 2047) * 2;
    float v0 = in[(size_t)jp * C + c];
    float v1 = in[(size_t)(jp + 1) * C + c];
    __nv_bfloat162 h2 = __floats2bfloat162_rn(v0, v1);
    *reinterpret_cast<__nv_bfloat162*>(out + (size_t)c * GN + jp) = h2;
}

// ---------------- bf16 mma helper ----------------
__device__ __forceinline__ void mma16816(float* d, const uint32_t* a,
                                         uint32_t b0, uint32_t b1) {
    asm volatile(
        "mma.sync.aligned.m16n8k16.row.col.f32.bf16.bf16.f32 "
        "{%0,%1,%2,%3}, {%4,%5,%6,%7}, {%8,%9}, {%0,%1,%2,%3};"
        : "+f"(d[0]), "+f"(d[1]), "+f"(d[2]), "+f"(d[3])
        : "r"(a[0]), "r"(a[1]), "r"(a[2]), "r"(a[3]), "r"(b0), "r"(b1));
}

// ---------------- fused masked softmax + att@wh via tensor cores ----------
// Block = 32*WARPS threads; TILE_I = 32*WARPS rows; TILE_J = 64.
// P tile (bf16) in smem; wh tile (bf16, transposed [f][j]) in smem with an
// extra ones-column block (rows 64..71, col 64 = 1) so den rides in n-tile 8.
// Warp w owns rows [w*32, w*32+32) = two m16 tiles; n-tiles 0..8 (72 cols).
template<int WARPS>
__global__ void __launch_bounds__(32 * WARPS)
attn_mma_kernel(const __nv_bfloat16* __restrict__ whT,   // [64][GN] per head
                const float* __restrict__ s1g, const float* __restrict__ s2g,
                const float* __restrict__ gmaxp,
                const uint32_t* __restrict__ adjbits,
                float* __restrict__ out, int outStride, int applyElu) {
    constexpr int TI = 32 * WARPS;
    __shared__ __nv_bfloat16 ps[TI * 72];        // row stride 72 bf16 = 144B
    __shared__ __nv_bfloat16 whs[72 * 72];       // [f][j] stride 72

    const int t  = threadIdx.x;
    const int i0 = blockIdx.x * TI;
    const int h  = blockIdx.y;

    const __nv_bfloat16* whTh = whT + (size_t)h * 64 * GN;
    const float* s1h = s1g + h * GN;
    const float* s2h = s2g + h * GN;

    uint32_t* psW = reinterpret_cast<uint32_t*>(ps);
    uint32_t* whW = reinterpret_cast<uint32_t*>(whs);

    // constant ones/zero rows 64..71 of whs (written once)
    for (int idx = t; idx < 8 * 36; idx += TI) {
        int rr = idx / 36, wd = idx - rr * 36;
        whW[(64 + rr) * 36 + wd] = (rr == 0) ? 0x3F803F80u : 0u;
    }

    const float s1i = s1h[i0 + t];
    const float gme = s1i + gmaxp[0];
    const float m   = gme > 0.f ? gme : 0.2f * gme;   // valid softmax shift (monotone leaky)

    const int w = t >> 5, ln = t & 31;
    const int r = ln >> 2, c = ln & 3;

    float acc[2][9][4];
#pragma unroll
    for (int mt = 0; mt < 2; ++mt)
#pragma unroll
        for (int nt = 0; nt < 9; ++nt)
#pragma unroll
            for (int q = 0; q < 4; ++q) acc[mt][nt][q] = 0.f;

    const uint32_t* adjRow = adjbits + (size_t)(i0 + t) * ADJW;

    for (int jt = 0; jt < GN / 64; ++jt) {
        const int j0 = jt * 64;

        // ---- load wh tile (rows 0..63 of whs) ----
#pragma unroll
        for (int it = 0; it < 512 / TI; ++it) {
            int idx = it * TI + t;
            int f = idx >> 3, u = idx & 7;
            uint4 v = *(const uint4*)(whTh + (size_t)f * GN + j0 + u * 8);
            *(uint4*)((char*)whs + f * 144 + u * 16) = v;
        }

        // ---- phase 1: p row for this thread's row, bf16 into ps ----
        const uint32_t ab0 = adjRow[(j0 >> 5)];
        const uint32_t ab1 = adjRow[(j0 >> 5) + 1];
#pragma unroll
        for (int u = 0; u < 8; ++u) {
            uint32_t buf[4];
#pragma unroll
            for (int q = 0; q < 4; ++q) {
                int jw = u * 4 + q;
                float2 s2p = *(const float2*)(s2h + j0 + jw * 2);
                float e0 = s1i + s2p.x;
                float e1 = s1i + s2p.y;
                e0 = e0 > 0.f ? e0 : 0.2f * e0;
                e1 = e1 > 0.f ? e1 : 0.2f * e1;
                int j = jw * 2;
                uint32_t wv = (j < 32) ? ab0 : ab1;
                int b = j & 31;
                float p0 = ((wv >> b) & 1u)       ? __expf(e0 - m) : 0.f;
                float p1 = ((wv >> (b + 1)) & 1u) ? __expf(e1 - m) : 0.f;
                __nv_bfloat162 h2 = __floats2bfloat162_rn(p0, p1);
                buf[q] = *reinterpret_cast<uint32_t*>(&h2);
            }
            *(uint4*)((char*)ps + t * 144 + u * 16) =
                make_uint4(buf[0], buf[1], buf[2], buf[3]);
        }
        __syncthreads();

        // ---- phase 2: tensor-core P @ wh_ext ----
#pragma unroll
        for (int kt = 0; kt < 4; ++kt) {
            uint32_t a[2][4];
#pragma unroll
            for (int mt = 0; mt < 2; ++mt) {
                int ri = w * 32 + mt * 16 + r;
                a[mt][0] = psW[ri * 36 + kt * 8 + c];
                a[mt][1] = psW[(ri + 8) * 36 + kt * 8 + c];
                a[mt][2] = psW[ri * 36 + kt * 8 + 4 + c];
                a[mt][3] = psW[(ri + 8) * 36 + kt * 8 + 4 + c];
            }
#pragma unroll
            for (int nt = 0; nt < 9; ++nt) {
                int nr = nt * 8 + r;
                uint32_t b0 = whW[nr * 36 + kt * 8 + c];
                uint32_t b1 = whW[nr * 36 + kt * 8 + 4 + c];
                mma16816(acc[0][nt], a[0], b0, b1);
                mma16816(acc[1][nt], a[1], b0, b1);
            }
        }
        __syncthreads();
    }

    // ---- epilogue: normalize by den (n-tile 8, col 0), optional ELU, store ----
#pragma unroll
    for (int mt = 0; mt < 2; ++mt) {
        float dA = __shfl_sync(0xffffffffu, acc[mt][8][0], ln & 28);
        float dB = __shfl_sync(0xffffffffu, acc[mt][8][2], ln & 28);
        float iA = 1.f / dA, iB = 1.f / dB;
        int rowA = i0 + w * 32 + mt * 16 + r;
#pragma unroll
        for (int nt = 0; nt < 8; ++nt) {
            int col = h * 64 + nt * 8 + c * 2;
            float v0 = acc[mt][nt][0] * iA;
            float v1 = acc[mt][nt][1] * iA;
            float v2 = acc[mt][nt][2] * iB;
            float v3 = acc[mt][nt][3] * iB;
            if (applyElu) {
                v0 = v0 > 0.f ? v0 : (__expf(v0) - 1.f);
                v1 = v1 > 0.f ? v1 : (__expf(v1) - 1.f);
                v2 = v2 > 0.f ? v2 : (__expf(v2) - 1.f);
                v3 = v3 > 0.f ? v3 : (__expf(v3) - 1.f);
            }
            *(float2*)&out[(size_t)rowA * outStride + col]       = make_float2(v0, v1);
            *(float2*)&out[(size_t)(rowA + 8) * outStride + col] = make_float2(v2, v3);
        }
    }
}

// ---------------- final: ELU then log_softmax per row of 64, in place ----
__global__ void elu_lsm_kernel(float* __restrict__ out) {
    int row  = blockIdx.x * 8 + (threadIdx.x >> 5);
    int lane = threadIdx.x & 31;
    float* p = out + (size_t)row * 64;
    float v0 = p[lane], v1 = p[lane + 32];
    v0 = v0 > 0.f ? v0 : (__expf(v0) - 1.f);
    v1 = v1 > 0.f ? v1 : (__expf(v1) - 1.f);
    float mx = fmaxf(v0, v1);
#pragma unroll
    for (int o = 16; o; o >>= 1) mx = fmaxf(mx, __shfl_xor_sync(0xffffffffu, mx, o));
    float s = __expf(v0 - mx) + __expf(v1 - mx);
#pragma unroll
    for (int o = 16; o; o >>= 1) s += __shfl_xor_sync(0xffffffffu, s, o);
    float l = mx + __logf(s);
    p[lane]      = v0 - l;
    p[lane + 32] = v1 - l;
}

// ---------------- launch ----------------
extern "C" void kernel_launch(void* const* d_in, const int* in_sizes, int n_in,
                              void* d_out, int out_size) {
    const float* x   = (const float*)d_in[0];
    const int*   adj = (const int*)d_in[1];
    const float* W   = (const float*)d_in[2];
    const float* a1  = (const float*)d_in[3];
    const float* a2  = (const float*)d_in[4];
    const float* W2  = (const float*)d_in[5];
    const float* a21 = (const float*)d_in[6];
    const float* a22 = (const float*)d_in[7];
    float* out = (float*)d_out;

    uint32_t* adjbits; float *wh1, *s1, *s2, *gm, *hbuf, *wh2, *s21, *s22, *gm2;
    __nv_bfloat16 *whTb, *whT2b;
    cudaGetSymbolAddress((void**)&adjbits, g_adjbits);
    cudaGetSymbolAddress((void**)&wh1,   g_wh1);
    cudaGetSymbolAddress((void**)&whTb,  g_whTb);
    cudaGetSymbolAddress((void**)&s1,    g_s1);
    cudaGetSymbolAddress((void**)&s2,    g_s2);
    cudaGetSymbolAddress((void**)&gm,    g_gmax);
    cudaGetSymbolAddress((void**)&hbuf,  g_hbuf);
    cudaGetSymbolAddress((void**)&wh2,   g_wh2);
    cudaGetSymbolAddress((void**)&whT2b, g_whT2b);
    cudaGetSymbolAddress((void**)&s21,   g_s21);
    cudaGetSymbolAddress((void**)&s22,   g_s22);
    cudaGetSymbolAddress((void**)&gm2,   g_gmax2);

    // 1. pack adjacency to bitmask
    pack_adj_kernel<<<(GN * GN) / 256, 256>>>(adj, adjbits);
    // 2. layer-1 feature GEMM (fp32)
    gemm_nt_kernel<<<dim3(FCAT / 64, GN / 64), 256>>>(x, W, wh1, GN, FCAT, FCAT);
    // 3. scores + global max
    scores_kernel<<<(GN * GH) / 8, 256>>>(wh1, FCAT, GH, a1, a2, s1, s2);
    rowmax_kernel<<<GH, 256>>>(s2, gm);
    // 4. wh -> transposed bf16
    cvt_t_kernel<<<FCAT * 8, 256>>>(wh1, whTb, FCAT);
    // 5. fused masked softmax + att@wh (tensor cores), ELU, all heads
    attn_mma_kernel<4><<<dim3(GN / 128, GH), 128>>>(whTb, s1, s2, gm, adjbits,
                                                    hbuf, FCAT, 1);
    // 6. layer-2 GEMM
    gemm_nt_kernel<<<dim3(1, GN / 64), 256>>>(hbuf, W2, wh2, GN, HIDF, FCAT);
    // 7. layer-2 scores + attention
    scores_kernel<<<GN / 8, 256>>>(wh2, HIDF, 1, a21, a22, s21, s22);
    rowmax_kernel<<<1, 256>>>(s22, gm2);
    cvt_t_kernel<<<HIDF * 8, 256>>>(wh2, whT2b, HIDF);
    attn_mma_kernel<1><<<dim3(GN / 32, 1), 32>>>(whT2b, s21, s22, gm2, adjbits,
                                                 out, HIDF, 0);
    // 8. ELU + log_softmax in place
    elu_lsm_kernel<<<GN / 8, 256>>>(out);
}

// round 3
// speedup vs baseline: 6.8113x; 2.2944x over previous
#include <cuda_runtime.h>
#include <cuda_bf16.h>
#include <stdint.h>

#define GN 4096
#define GH 8
#define FCAT 512
#define HIDF 64
#define ADJW (GN/32)

// ---------------- scratch ----------------
__device__ uint32_t      g_adjbits[GN * ADJW];
__device__ __nv_bfloat16 g_xb[GN * FCAT];
__device__ __nv_bfloat16 g_Wb[FCAT * FCAT];
__device__ __nv_bfloat16 g_W2b[HIDF * FCAT];
__device__ float         g_wh1[GN * FCAT];
__device__ __nv_bfloat16 g_whTb[FCAT * GN];
__device__ float         g_s1[GH * GN];
__device__ float         g_s2[GH * GN];
__device__ unsigned      g_gmaxi[16];
__device__ __nv_bfloat16 g_hbufb[GN * FCAT];
__device__ float         g_wh2[GN * HIDF];
__device__ __nv_bfloat16 g_whT2b[HIDF * GN];
__device__ float         g_s21[GN];
__device__ float         g_s22[GN];
__device__ float         g_part[4 * GN * 72];

__device__ __forceinline__ unsigned fenc(float f) {
    unsigned b = __float_as_uint(f);
    return (b & 0x80000000u) ? ~b : (b | 0x80000000u);
}
__device__ __forceinline__ float fdec(unsigned k) {
    return __uint_as_float((k & 0x80000000u) ? (k & 0x7fffffffu) : ~k);
}

// ---------------- pack adjacency + init gmax ----------------
__global__ void pack_adj_kernel(const int* __restrict__ adj,
                                uint32_t* __restrict__ bits,
                                unsigned* __restrict__ gmaxi) {
    if (blockIdx.x == 0 && threadIdx.x < 16) gmaxi[threadIdx.x] = 0u;
    int t = blockIdx.x * 256 + threadIdx.x;
    uint32_t b = __ballot_sync(0xffffffffu, adj[t] > 0);
    if ((threadIdx.x & 31) == 0) bits[t >> 5] = b;
}

// ---------------- fp32 -> bf16 elementwise ----------------
__global__ void cvt_bf16_kernel(const float* __restrict__ in,
                                __nv_bfloat16* __restrict__ out) {
    int id = (blockIdx.x * 256 + threadIdx.x) * 2;
    float2 v = *(const float2*)(in + id);
    *(__nv_bfloat162*)(out + id) = __floats2bfloat162_rn(v.x, v.y);
}

// ---------------- fp32 [GN][C] -> bf16 transposed [C][GN] (tiled) ----------
__global__ void transpose_cvt_kernel(const float* __restrict__ in,
                                     __nv_bfloat16* __restrict__ out, int C) {
    __shared__ float tile[32][33];
    int tx = threadIdx.x, ty = threadIdx.y;
    int c0 = blockIdx.x * 32;
    int r0 = blockIdx.y * 32;
#pragma unroll
    for (int k = 0; k < 4; ++k)
        tile[ty + k * 8][tx] = in[(size_t)(r0 + ty + k * 8) * C + c0 + tx];
    __syncthreads();
#pragma unroll
    for (int k = 0; k < 4; ++k)
        out[(size_t)(c0 + ty + k * 8) * GN + r0 + tx] =
            __float2bfloat16(tile[tx][ty + k * 8]);
}

// ---------------- bf16 mma helper ----------------
__device__ __forceinline__ void mma16816(float* d, const uint32_t* a,
                                         uint32_t b0, uint32_t b1) {
    asm volatile(
        "mma.sync.aligned.m16n8k16.row.col.f32.bf16.bf16.f32 "
        "{%0,%1,%2,%3}, {%4,%5,%6,%7}, {%8,%9}, {%0,%1,%2,%3};"
        : "+f"(d[0]), "+f"(d[1]), "+f"(d[2]), "+f"(d[3])
        : "r"(a[0]), "r"(a[1]), "r"(a[2]), "r"(a[3]), "r"(b0), "r"(b1));
}

// ---------------- bf16 NT GEMM: C[m][n] = sum_k A[m][k]*B[n][k] ------------
// block 256 thr (8 warps), tile M=128 N=64 Kc=64; warp w -> m-tile w.
__global__ void __launch_bounds__(256)
gemm_bf16_nt(const __nv_bfloat16* __restrict__ A,
             const __nv_bfloat16* __restrict__ B,
             float* __restrict__ C, int K, int Ncols) {
    __shared__ __nv_bfloat16 As[128 * 72];
    __shared__ __nv_bfloat16 Bs[64 * 72];
    uint32_t* AsW = reinterpret_cast<uint32_t*>(As);
    uint32_t* BsW = reinterpret_cast<uint32_t*>(Bs);

    const int t  = threadIdx.x;
    const int m0 = blockIdx.y * 128;
    const int n0 = blockIdx.x * 64;
    const int w = t >> 5, ln = t & 31;
    const int r = ln >> 2, c = ln & 3;

    float acc[8][4];
#pragma unroll
    for (int nt = 0; nt < 8; ++nt)
#pragma unroll
        for (int q = 0; q < 4; ++q) acc[nt][q] = 0.f;

    for (int kc = 0; kc < K; kc += 64) {
#pragma unroll
        for (int it = 0; it < 4; ++it) {
            int idx = it * 256 + t;
            int row = idx >> 3, u = idx & 7;
            uint4 v = *(const uint4*)(A + (size_t)(m0 + row) * K + kc + u * 8);
            *(uint4*)(AsW + row * 36 + u * 4) = v;
        }
#pragma unroll
        for (int it = 0; it < 2; ++it) {
            int idx = it * 256 + t;
            int row = idx >> 3, u = idx & 7;
            uint4 v = *(const uint4*)(B + (size_t)(n0 + row) * K + kc + u * 8);
            *(uint4*)(BsW + row * 36 + u * 4) = v;
        }
        __syncthreads();
#pragma unroll
        for (int kt = 0; kt < 4; ++kt) {
            uint32_t a[4];
            int ri = w * 16 + r;
            a[0] = AsW[ri * 36 + kt * 8 + c];
            a[1] = AsW[(ri + 8) * 36 + kt * 8 + c];
            a[2] = AsW[ri * 36 + kt * 8 + 4 + c];
            a[3] = AsW[(ri + 8) * 36 + kt * 8 + 4 + c];
#pragma unroll
            for (int nt = 0; nt < 8; ++nt) {
                int nr = nt * 8 + r;
                uint32_t b0 = BsW[nr * 36 + kt * 8 + c];
                uint32_t b1 = BsW[nr * 36 + kt * 8 + 4 + c];
                mma16816(acc[nt], a, b0, b1);
            }
        }
        __syncthreads();
    }
    int rA = m0 + w * 16 + r;
#pragma unroll
    for (int nt = 0; nt < 8; ++nt) {
        int col = n0 + nt * 8 + c * 2;
        *(float2*)&C[(size_t)rA * Ncols + col]       = make_float2(acc[nt][0], acc[nt][1]);
        *(float2*)&C[(size_t)(rA + 8) * Ncols + col] = make_float2(acc[nt][2], acc[nt][3]);
    }
}

// ---------------- scores + fused global max ----------------
__global__ void scores_kernel(const float* __restrict__ wh, int stride, int nH,
                              const float* __restrict__ a1, const float* __restrict__ a2,
                              float* __restrict__ s1, float* __restrict__ s2,
                              unsigned* __restrict__ gmaxi) {
    int w    = blockIdx.x * 8 + (threadIdx.x >> 5);
    int lane = threadIdx.x & 31;
    int i = w / nH, h = w % nH;
    const float* base = wh + (size_t)i * stride + h * 64;
    float v0 = base[lane], v1 = base[lane + 32];
    float p1 = v0 * a1[h * 64 + lane] + v1 * a1[h * 64 + lane + 32];
    float p2 = v0 * a2[h * 64 + lane] + v1 * a2[h * 64 + lane + 32];
#pragma unroll
    for (int o = 16; o; o >>= 1) {
        p1 += __shfl_down_sync(0xffffffffu, p1, o);
        p2 += __shfl_down_sync(0xffffffffu, p2, o);
    }
    if (lane == 0) {
        s1[h * GN + i] = p1;
        s2[h * GN + i] = p2;
        atomicMax(&gmaxi[h], fenc(p2));
    }
}

// ---------------- fused masked softmax + att@wh via tensor cores ----------
// TI=64 rows, 128 threads (4 warps, warp w -> m-tile w). j-range split JS ways
// across blockIdx.z (valid: fixed softmax shift -> partials are linear).
// JS==1: normalize + ELU + bf16 store. JS==4: raw num/den partial to scratch.
template<int JS>
__global__ void __launch_bounds__(128)
attn_mma_kernel(const __nv_bfloat16* __restrict__ whT,
                const float* __restrict__ s1g, const float* __restrict__ s2g,
                const unsigned* __restrict__ gmaxi,
                const uint32_t* __restrict__ adjbits,
                float* __restrict__ part, __nv_bfloat16* __restrict__ outB) {
    __shared__ __nv_bfloat16 ps[64 * 72];
    __shared__ __nv_bfloat16 whs[72 * 72];
    __shared__ float s2s[GN / JS];

    const int t  = threadIdx.x;
    const int i0 = blockIdx.x * 64;
    const int h  = blockIdx.y;
    const int jt0 = blockIdx.z * (64 / JS);
    const int jbase = jt0 * 64;

    const __nv_bfloat16* whTh = whT + (size_t)h * 64 * GN;
    const float* s1h = s1g + h * GN;
    const float* s2h = s2g + h * GN;

    uint32_t* psW = reinterpret_cast<uint32_t*>(ps);
    uint32_t* whW = reinterpret_cast<uint32_t*>(whs);

    // stage s2 range once
#pragma unroll
    for (int idx = t; idx < GN / (JS * 4); idx += 128)
        ((float4*)s2s)[idx] = ((const float4*)(s2h + jbase))[idx];

    // constant rows 64..71 of whs: row 64 = ones (den column), rest zero
    for (int idx = t; idx < 8 * 36; idx += 128) {
        int rr = idx / 36, wd = idx - rr * 36;
        whW[(64 + rr) * 36 + wd] = (rr == 0) ? 0x3F803F80u : 0u;
    }

    const int rt = t >> 1, jh = t & 1;      // phase-1 row / j-half
    const float s1i = s1h[i0 + rt];
    const float gmax = fdec(gmaxi[h]);
    const float gme = s1i + gmax;
    const float m = gme > 0.f ? gme : 0.2f * gme;

    const int w = t >> 5, ln = t & 31;
    const int r = ln >> 2, c = ln & 3;

    float acc[9][4];
#pragma unroll
    for (int nt = 0; nt < 9; ++nt)
#pragma unroll
        for (int q = 0; q < 4; ++q) acc[nt][q] = 0.f;

    const uint32_t* adjRow = adjbits + (size_t)(i0 + rt) * ADJW;

    for (int ltj = 0; ltj < 64 / JS; ++ltj) {
        const int j0 = jbase + ltj * 64;

        // wh tile: 64 f-rows x 64 j (bf16)
#pragma unroll
        for (int it = 0; it < 4; ++it) {
            int idx = it * 128 + t;
            int f = idx >> 3, u = idx & 7;
            uint4 v = *(const uint4*)(whTh + (size_t)f * GN + j0 + u * 8);
            *(uint4*)(whW + f * 36 + u * 4) = v;
        }

        // phase 1: 32 p's per thread (row rt, half jh)
        const uint32_t abw = adjRow[(j0 >> 5) + jh];
        const float* s2t = s2s + ltj * 64 + jh * 32;
#pragma unroll
        for (int u = 0; u < 4; ++u) {
            uint32_t buf[4];
#pragma unroll
            for (int q = 0; q < 4; ++q) {
                int jj = u * 8 + q * 2;
                float2 sv = *(const float2*)(s2t + jj);
                float e0 = s1i + sv.x;
                float e1 = s1i + sv.y;
                e0 = e0 > 0.f ? e0 : 0.2f * e0;
                e1 = e1 > 0.f ? e1 : 0.2f * e1;
                float p0 = ((abw >> jj) & 1u)       ? __expf(e0 - m) : 0.f;
                float p1 = ((abw >> (jj + 1)) & 1u) ? __expf(e1 - m) : 0.f;
                __nv_bfloat162 h2 = __floats2bfloat162_rn(p0, p1);
                buf[q] = *reinterpret_cast<uint32_t*>(&h2);
            }
            *(uint4*)(psW + rt * 36 + jh * 16 + u * 4) =
                make_uint4(buf[0], buf[1], buf[2], buf[3]);
        }
        __syncthreads();

        // phase 2: P(16x64) @ wh_ext(64x72) per warp
#pragma unroll
        for (int kt = 0; kt < 4; ++kt) {
            uint32_t a[4];
            int ri = w * 16 + r;
            a[0] = psW[ri * 36 + kt * 8 + c];
            a[1] = psW[(ri + 8) * 36 + kt * 8 + c];
            a[2] = psW[ri * 36 + kt * 8 + 4 + c];
            a[3] = psW[(ri + 8) * 36 + kt * 8 + 4 + c];
#pragma unroll
            for (int nt = 0; nt < 9; ++nt) {
                int nr = nt * 8 + r;
                uint32_t b0 = whW[nr * 36 + kt * 8 + c];
                uint32_t b1 = whW[nr * 36 + kt * 8 + 4 + c];
                mma16816(acc[nt], a, b0, b1);
            }
        }
        __syncthreads();
    }

    int rA = i0 + w * 16 + r;
    if (JS == 1) {
        float dA = __shfl_sync(0xffffffffu, acc[8][0], ln & 28);
        float dB = __shfl_sync(0xffffffffu, acc[8][2], ln & 28);
        float iA = 1.f / dA, iB = 1.f / dB;
#pragma unroll
        for (int nt = 0; nt < 8; ++nt) {
            int col = h * 64 + nt * 8 + c * 2;
            float v0 = acc[nt][0] * iA;
            float v1 = acc[nt][1] * iA;
            float v2 = acc[nt][2] * iB;
            float v3 = acc[nt][3] * iB;
            v0 = v0 > 0.f ? v0 : (__expf(v0) - 1.f);
            v1 = v1 > 0.f ? v1 : (__expf(v1) - 1.f);
            v2 = v2 > 0.f ? v2 : (__expf(v2) - 1.f);
            v3 = v3 > 0.f ? v3 : (__expf(v3) - 1.f);
            *(__nv_bfloat162*)(outB + (size_t)rA * FCAT + col) =
                __floats2bfloat162_rn(v0, v1);
            *(__nv_bfloat162*)(outB + (size_t)(rA + 8) * FCAT + col) =
                __floats2bfloat162_rn(v2, v3);
        }
    } else {
        float* pA = part + ((size_t)blockIdx.z * GN + rA) * 72;
        float* pB = pA + 8 * 72;
#pragma unroll
        for (int nt = 0; nt < 8; ++nt) {
            int col = nt * 8 + c * 2;
            *(float2*)(pA + col) = make_float2(acc[nt][0], acc[nt][1]);
            *(float2*)(pB + col) = make_float2(acc[nt][2], acc[nt][3]);
        }
        if (c == 0) { pA[64] = acc[8][0]; pB[64] = acc[8][2]; }
    }
}

// ---------------- reduce partials + ELU + log_softmax ----------------
__global__ void reduce_lsm_kernel(const float* __restrict__ part,
                                  float* __restrict__ out) {
    int row = blockIdx.x * 8 + (threadIdx.x >> 5);
    int ln  = threadIdx.x & 31;
    float n0 = 0.f, n1 = 0.f, d = 0.f;
#pragma unroll
    for (int js = 0; js < 4; ++js) {
        const float* b = part + ((size_t)js * GN + row) * 72;
        n0 += b[ln]; n1 += b[ln + 32]; d += b[64];
    }
    float inv = 1.f / d;
    float v0 = n0 * inv, v1 = n1 * inv;
    v0 = v0 > 0.f ? v0 : (__expf(v0) - 1.f);
    v1 = v1 > 0.f ? v1 : (__expf(v1) - 1.f);
    float mx = fmaxf(v0, v1);
#pragma unroll
    for (int o = 16; o; o >>= 1) mx = fmaxf(mx, __shfl_xor_sync(0xffffffffu, mx, o));
    float s = __expf(v0 - mx) + __expf(v1 - mx);
#pragma unroll
    for (int o = 16; o; o >>= 1) s += __shfl_xor_sync(0xffffffffu, s, o);
    float l = mx + __logf(s);
    out[(size_t)row * 64 + ln]      = v0 - l;
    out[(size_t)row * 64 + ln + 32] = v1 - l;
}

// ---------------- launch ----------------
extern "C" void kernel_launch(void* const* d_in, const int* in_sizes, int n_in,
                              void* d_out, int out_size) {
    const float* x   = (const float*)d_in[0];
    const int*   adj = (const int*)d_in[1];
    const float* W   = (const float*)d_in[2];
    const float* a1  = (const float*)d_in[3];
    const float* a2  = (const float*)d_in[4];
    const float* W2  = (const float*)d_in[5];
    const float* a21 = (const float*)d_in[6];
    const float* a22 = (const float*)d_in[7];
    float* out = (float*)d_out;

    uint32_t* adjbits; unsigned* gmaxi;
    float *wh1, *s1, *s2, *wh2, *s21, *s22, *part;
    __nv_bfloat16 *xb, *Wb, *W2b, *whTb, *hbufb, *whT2b;
    cudaGetSymbolAddress((void**)&adjbits, g_adjbits);
    cudaGetSymbolAddress((void**)&gmaxi, g_gmaxi);
    cudaGetSymbolAddress((void**)&xb,    g_xb);
    cudaGetSymbolAddress((void**)&Wb,    g_Wb);
    cudaGetSymbolAddress((void**)&W2b,   g_W2b);
    cudaGetSymbolAddress((void**)&wh1,   g_wh1);
    cudaGetSymbolAddress((void**)&whTb,  g_whTb);
    cudaGetSymbolAddress((void**)&s1,    g_s1);
    cudaGetSymbolAddress((void**)&s2,    g_s2);
    cudaGetSymbolAddress((void**)&hbufb, g_hbufb);
    cudaGetSymbolAddress((void**)&wh2,   g_wh2);
    cudaGetSymbolAddress((void**)&whT2b, g_whT2b);
    cudaGetSymbolAddress((void**)&s21,   g_s21);
    cudaGetSymbolAddress((void**)&s22,   g_s22);
    cudaGetSymbolAddress((void**)&part,  g_part);

    // pack adjacency + init gmax
    pack_adj_kernel<<<(GN * GN) / 256, 256>>>(adj, adjbits, gmaxi);
    // fp32 -> bf16 inputs
    cvt_bf16_kernel<<<(GN * FCAT) / 512, 256>>>(x, xb);
    cvt_bf16_kernel<<<(FCAT * FCAT) / 512, 256>>>(W, Wb);
    cvt_bf16_kernel<<<(HIDF * FCAT) / 512, 256>>>(W2, W2b);
    // layer-1 GEMM (tensor cores)
    gemm_bf16_nt<<<dim3(FCAT / 64, GN / 128), 256>>>(xb, Wb, wh1, FCAT, FCAT);
    // scores (+ fused global max) and transposed bf16 wh
    scores_kernel<<<(GN * GH) / 8, 256>>>(wh1, FCAT, GH, a1, a2, s1, s2, gmaxi);
    transpose_cvt_kernel<<<dim3(FCAT / 32, GN / 32), dim3(32, 8)>>>(wh1, whTb, FCAT);
    // layer-1 fused attention (ELU, bf16 out)
    attn_mma_kernel<1><<<dim3(GN / 64, GH, 1), 128>>>(whTb, s1, s2, gmaxi,
                                                      adjbits, nullptr, hbufb);
    // layer-2 GEMM
    gemm_bf16_nt<<<dim3(1, GN / 128), 256>>>(hbufb, W2b, wh2, FCAT, HIDF);
    // layer-2 scores + transposed bf16
    scores_kernel<<<GN / 8, 256>>>(wh2, HIDF, 1, a21, a22, s21, s22, gmaxi + 8);
    transpose_cvt_kernel<<<dim3(HIDF / 32, GN / 32), dim3(32, 8)>>>(wh2, whT2b, HIDF);
    // layer-2 attention, j-split 4 ways into partials
    attn_mma_kernel<4><<<dim3(GN / 64, 1, 4), 128>>>(whT2b, s21, s22, gmaxi + 8,
                                                     adjbits, part, nullptr);
    // reduce partials + ELU + log_softmax
    reduce_lsm_kernel<<<GN / 8, 256>>>(part, out);
}

// round 4
// speedup vs baseline: 8.9274x; 1.3107x over previous
#include <cuda_runtime.h>
#include <cuda_bf16.h>
#include <stdint.h>

#define GN 4096
#define GH 8
#define FCAT 512
#define HIDF 64
#define ADJW (GN/32)
#define JS2 8
#define LOG2E 1.4426950408889634f

// ---------------- scratch ----------------
__device__ uint32_t      g_adjbits[GN * ADJW];
__device__ __nv_bfloat16 g_xb[GN * FCAT];
__device__ __nv_bfloat16 g_Wb[FCAT * FCAT];
__device__ __nv_bfloat16 g_W2b[HIDF * FCAT];
__device__ float         g_wh1[GN * FCAT];
__device__ __nv_bfloat16 g_whTb[FCAT * GN];
__device__ float         g_s1[GH * GN];
__device__ float         g_s2[GH * GN];
__device__ unsigned      g_gmaxi[16];
__device__ __nv_bfloat16 g_hbufb[GN * FCAT];
__device__ float         g_wh2[GN * HIDF];
__device__ __nv_bfloat16 g_whT2b[HIDF * GN];
__device__ float         g_s21[GN];
__device__ float         g_s22[GN];
__device__ float         g_part[JS2 * GN * 72];

__device__ __forceinline__ unsigned fenc(float f) {
    unsigned b = __float_as_uint(f);
    return (b & 0x80000000u) ? ~b : (b | 0x80000000u);
}
__device__ __forceinline__ float fdec(unsigned k) {
    return __uint_as_float((k & 0x80000000u) ? (k & 0x7fffffffu) : ~k);
}
__device__ __forceinline__ float ex2f(float x) {
    float y; asm("ex2.approx.f32 %0, %1;" : "=f"(y) : "f"(x)); return y;
}
__device__ __forceinline__ uint32_t sptr(const void* p) {
    return (uint32_t)__cvta_generic_to_shared(p);
}
__device__ __forceinline__ void ldsm4(uint32_t* r, uint32_t a) {
    asm volatile("ldmatrix.sync.aligned.m8n8.x4.shared.b16 {%0,%1,%2,%3}, [%4];"
                 : "=r"(r[0]), "=r"(r[1]), "=r"(r[2]), "=r"(r[3]) : "r"(a));
}
__device__ __forceinline__ void ldsm2(uint32_t* r, uint32_t a) {
    asm volatile("ldmatrix.sync.aligned.m8n8.x2.shared.b16 {%0,%1}, [%2];"
                 : "=r"(r[0]), "=r"(r[1]) : "r"(a));
}
__device__ __forceinline__ void cpa16(uint32_t dst, const void* src) {
    asm volatile("cp.async.cg.shared.global [%0], [%1], 16;" :: "r"(dst), "l"(src));
}
__device__ __forceinline__ void cpa_commit() {
    asm volatile("cp.async.commit_group;");
}
template<int N>
__device__ __forceinline__ void cpa_wait() {
    asm volatile("cp.async.wait_group %0;" :: "n"(N));
}
__device__ __forceinline__ void mma16816(float* d, const uint32_t* a,
                                         uint32_t b0, uint32_t b1) {
    asm volatile(
        "mma.sync.aligned.m16n8k16.row.col.f32.bf16.bf16.f32 "
        "{%0,%1,%2,%3}, {%4,%5,%6,%7}, {%8,%9}, {%0,%1,%2,%3};"
        : "+f"(d[0]), "+f"(d[1]), "+f"(d[2]), "+f"(d[3])
        : "r"(a[0]), "r"(a[1]), "r"(a[2]), "r"(a[3]), "r"(b0), "r"(b1));
}

// ---------------- pack adjacency + init gmax ----------------
__global__ void pack_adj_kernel(const int* __restrict__ adj,
                                uint32_t* __restrict__ bits,
                                unsigned* __restrict__ gmaxi) {
    if (blockIdx.x == 0 && threadIdx.x < 16) gmaxi[threadIdx.x] = 0u;
    int t = blockIdx.x * 256 + threadIdx.x;
    uint32_t b = __ballot_sync(0xffffffffu, adj[t] > 0);
    if ((threadIdx.x & 31) == 0) bits[t >> 5] = b;
}

// ---------------- fp32 -> bf16 elementwise ----------------
__global__ void cvt_bf16_kernel(const float* __restrict__ in,
                                __nv_bfloat16* __restrict__ out) {
    int id = (blockIdx.x * 256 + threadIdx.x) * 2;
    float2 v = *(const float2*)(in + id);
    *(__nv_bfloat162*)(out + id) = __floats2bfloat162_rn(v.x, v.y);
}

// ---------------- fp32 [GN][C] -> bf16 transposed [C][GN] ----------------
__global__ void transpose_cvt_kernel(const float* __restrict__ in,
                                     __nv_bfloat16* __restrict__ out, int C) {
    __shared__ float tile[32][33];
    int tx = threadIdx.x, ty = threadIdx.y;
    int c0 = blockIdx.x * 32;
    int r0 = blockIdx.y * 32;
#pragma unroll
    for (int k = 0; k < 4; ++k)
        tile[ty + k * 8][tx] = in[(size_t)(r0 + ty + k * 8) * C + c0 + tx];
    __syncthreads();
#pragma unroll
    for (int k = 0; k < 4; ++k)
        out[(size_t)(c0 + ty + k * 8) * GN + r0 + tx] =
            __float2bfloat16(tile[tx][ty + k * 8]);
}

// ---------------- bf16 NT GEMM (ldmatrix fragments) ----------------
__global__ void __launch_bounds__(256)
gemm_bf16_nt(const __nv_bfloat16* __restrict__ A,
             const __nv_bfloat16* __restrict__ B,
             float* __restrict__ C, int K, int Ncols) {
    __shared__ __nv_bfloat16 As[128 * 72];
    __shared__ __nv_bfloat16 Bs[64 * 72];
    uint32_t* AsW = reinterpret_cast<uint32_t*>(As);
    uint32_t* BsW = reinterpret_cast<uint32_t*>(Bs);

    const int t  = threadIdx.x;
    const int m0 = blockIdx.y * 128;
    const int n0 = blockIdx.x * 64;
    const int w = t >> 5, ln = t & 31;
    const int r = ln >> 2, c = ln & 3;

    const uint32_t aB = sptr(As) + (uint32_t)(((w * 16 + (ln & 15)) * 72 +
                                               ((ln >> 4) & 1) * 8) * 2);
    const uint32_t bB = sptr(Bs) + (uint32_t)((((ln & 7) + ((ln >> 4) & 1) * 8) * 72 +
                                               ((ln >> 3) & 1) * 8) * 2);

    float acc[8][4];
#pragma unroll
    for (int nt = 0; nt < 8; ++nt)
#pragma unroll
        for (int q = 0; q < 4; ++q) acc[nt][q] = 0.f;

    for (int kc = 0; kc < K; kc += 64) {
#pragma unroll
        for (int it = 0; it < 4; ++it) {
            int idx = it * 256 + t;
            int row = idx >> 3, u = idx & 7;
            uint4 v = *(const uint4*)(A + (size_t)(m0 + row) * K + kc + u * 8);
            *(uint4*)(AsW + row * 36 + u * 4) = v;
        }
#pragma unroll
        for (int it = 0; it < 2; ++it) {
            int idx = it * 256 + t;
            int row = idx >> 3, u = idx & 7;
            uint4 v = *(const uint4*)(B + (size_t)(n0 + row) * K + kc + u * 8);
            *(uint4*)(BsW + row * 36 + u * 4) = v;
        }
        __syncthreads();
#pragma unroll
        for (int kt = 0; kt < 4; ++kt) {
            uint32_t a[4];
            ldsm4(a, aB + kt * 32);
#pragma unroll
            for (int p = 0; p < 4; ++p) {
                uint32_t b[4];
                ldsm4(b, bB + p * 2304 + kt * 32);
                mma16816(acc[2 * p],     a, b[0], b[1]);
                mma16816(acc[2 * p + 1], a, b[2], b[3]);
            }
        }
        __syncthreads();
    }
    int rA = m0 + w * 16 + r;
#pragma unroll
    for (int nt = 0; nt < 8; ++nt) {
        int col = n0 + nt * 8 + c * 2;
        *(float2*)&C[(size_t)rA * Ncols + col]       = make_float2(acc[nt][0], acc[nt][1]);
        *(float2*)&C[(size_t)(rA + 8) * Ncols + col] = make_float2(acc[nt][2], acc[nt][3]);
    }
}

// ---------------- scores (pre-scaled by log2e) + fused global max ----------
__global__ void scores_kernel(const float* __restrict__ wh, int stride, int nH,
                              const float* __restrict__ a1, const float* __restrict__ a2,
                              float* __restrict__ s1, float* __restrict__ s2,
                              unsigned* __restrict__ gmaxi) {
    int w    = blockIdx.x * 8 + (threadIdx.x >> 5);
    int lane = threadIdx.x & 31;
    int i = w / nH, h = w % nH;
    const float* base = wh + (size_t)i * stride + h * 64;
    float v0 = base[lane], v1 = base[lane + 32];
    float p1 = v0 * a1[h * 64 + lane] + v1 * a1[h * 64 + lane + 32];
    float p2 = v0 * a2[h * 64 + lane] + v1 * a2[h * 64 + lane + 32];
#pragma unroll
    for (int o = 16; o; o >>= 1) {
        p1 += __shfl_down_sync(0xffffffffu, p1, o);
        p2 += __shfl_down_sync(0xffffffffu, p2, o);
    }
    if (lane == 0) {
        p1 *= LOG2E; p2 *= LOG2E;
        s1[h * GN + i] = p1;
        s2[h * GN + i] = p2;
        atomicMax(&gmaxi[h], fenc(p2));
    }
}

// ---------------- fused masked softmax + att@wh, cp.async + ldmatrix -------
// TI=128 rows/block, 128 threads (4 warps x 2 m-tiles). j-split JS across z.
template<int JS>
__global__ void __launch_bounds__(128)
attn_mma_kernel(const __nv_bfloat16* __restrict__ whT,
                const float* __restrict__ s1g, const float* __restrict__ s2g,
                const unsigned* __restrict__ gmaxi,
                const uint32_t* __restrict__ adjbits,
                float* __restrict__ part, __nv_bfloat16* __restrict__ outB) {
    __shared__ __nv_bfloat16 ps[128 * 72];
    __shared__ __nv_bfloat16 whs[2][72 * 72];
    __shared__ float s2t[2][64];

    const int t  = threadIdx.x;
    const int i0 = blockIdx.x * 128;
    const int h  = blockIdx.y;
    const int jbase = blockIdx.z * (GN / JS);
    const int NT = (GN / JS) / 64;

    const __nv_bfloat16* whTh = whT + (size_t)h * 64 * GN;
    const float* s2h = s2g + h * GN;
    uint32_t* psW = reinterpret_cast<uint32_t*>(ps);

    // constant rows 64..71 of both whs buffers (row 64 = ones -> den column)
#pragma unroll
    for (int b = 0; b < 2; ++b)
        for (int idx = t; idx < 8 * 36; idx += 128) {
            int rr = idx / 36, wd = idx - rr * 36;
            reinterpret_cast<uint32_t*>(whs[b])[(64 + rr) * 36 + wd] =
                (rr == 0) ? 0x3F803F80u : 0u;
        }

    // --- tile loader (cp.async) ---
    auto issue_tile = [&](int tt) {
        int buf = tt & 1;
        int j0 = jbase + tt * 64;
#pragma unroll
        for (int it = 0; it < 4; ++it) {
            int idx = it * 128 + t;
            int f = idx >> 3, u = idx & 7;
            cpa16(sptr(&whs[buf][f * 72 + u * 8]), whTh + (size_t)f * GN + j0 + u * 8);
        }
        if (t < 16) cpa16(sptr(&s2t[buf][t * 4]), s2h + j0 + t * 4);
    };

    issue_tile(0);
    cpa_commit();

    const float s1i = s1g[h * GN + i0 + t];
    const float gme = s1i + fdec(gmaxi[h]);
    const float m = fmaxf(gme, 0.2f * gme);

    const int w = t >> 5, ln = t & 31;
    const int r = ln >> 2, c = ln & 3;

    const uint32_t psB = sptr(ps) + (uint32_t)(((w * 32 + (ln & 15)) * 72 +
                                                ((ln >> 4) & 1) * 8) * 2);
    const uint32_t whB0 = sptr(whs[0]) + (uint32_t)((((ln & 7) + ((ln >> 4) & 1) * 8) * 72 +
                                                     ((ln >> 3) & 1) * 8) * 2);
    const uint32_t dnB0 = sptr(whs[0]) + (uint32_t)(((64 + (ln & 7)) * 72 +
                                                     ((ln >> 3) & 1) * 8) * 2);
    const uint32_t bufStride = (uint32_t)(72 * 72 * 2);

    float acc[2][9][4];
#pragma unroll
    for (int mt = 0; mt < 2; ++mt)
#pragma unroll
        for (int nt = 0; nt < 9; ++nt)
#pragma unroll
            for (int q = 0; q < 4; ++q) acc[mt][nt][q] = 0.f;

    const uint32_t* adjRow = adjbits + (size_t)(i0 + t) * ADJW;

    for (int tt = 0; tt < NT; ++tt) {
        if (tt + 1 < NT) { issue_tile(tt + 1); cpa_commit(); cpa_wait<1>(); }
        else             { cpa_wait<0>(); }
        __syncthreads();

        const int buf = tt & 1;
        const int j0  = jbase + tt * 64;

        // ---- phase 1: this thread's row, 64 p's ----
        uint2 aw = *(const uint2*)(adjRow + (j0 >> 5));
        const float2* s2p = reinterpret_cast<const float2*>(s2t[buf]);
#pragma unroll
        for (int u = 0; u < 8; ++u) {
            uint32_t pk[4];
            uint32_t wv = (u < 4) ? aw.x : aw.y;
#pragma unroll
            for (int q = 0; q < 4; ++q) {
                int j = u * 8 + q * 2;
                float2 sv = s2p[u * 4 + q];
                float e0 = s1i + sv.x, e1 = s1i + sv.y;
                float a0 = fmaxf(e0, 0.2f * e0) - m;
                float a1 = fmaxf(e1, 0.2f * e1) - m;
                int bit = j & 31;
                float p0 = ((wv >> bit) & 1u)       ? ex2f(a0) : 0.f;
                float p1 = ((wv >> (bit + 1)) & 1u) ? ex2f(a1) : 0.f;
                __nv_bfloat162 h2 = __floats2bfloat162_rn(p0, p1);
                pk[q] = *reinterpret_cast<uint32_t*>(&h2);
            }
            *(uint4*)(psW + t * 36 + u * 4) = make_uint4(pk[0], pk[1], pk[2], pk[3]);
        }
        __syncthreads();

        // ---- phase 2: tensor cores via ldmatrix ----
        const uint32_t whB = whB0 + buf * bufStride;
        const uint32_t dnB = dnB0 + buf * bufStride;
#pragma unroll
        for (int kt = 0; kt < 4; ++kt) {
            uint32_t a0[4], a1[4];
            ldsm4(a0, psB + kt * 32);
            ldsm4(a1, psB + 2304 + kt * 32);
#pragma unroll
            for (int p = 0; p < 4; ++p) {
                uint32_t b[4];
                ldsm4(b, whB + p * 2304 + kt * 32);
                mma16816(acc[0][2 * p],     a0, b[0], b[1]);
                mma16816(acc[0][2 * p + 1], a0, b[2], b[3]);
                mma16816(acc[1][2 * p],     a1, b[0], b[1]);
                mma16816(acc[1][2 * p + 1], a1, b[2], b[3]);
            }
            uint32_t d[2];
            ldsm2(d, dnB + kt * 32);
            mma16816(acc[0][8], a0, d[0], d[1]);
            mma16816(acc[1][8], a1, d[0], d[1]);
        }
        __syncthreads();
    }

    if (JS == 1) {
#pragma unroll
        for (int mt = 0; mt < 2; ++mt) {
            float dA = __shfl_sync(0xffffffffu, acc[mt][8][0], ln & 28);
            float dB = __shfl_sync(0xffffffffu, acc[mt][8][2], ln & 28);
            float iA = 1.f / dA, iB = 1.f / dB;
            int rA = i0 + w * 32 + mt * 16 + r;
#pragma unroll
            for (int nt = 0; nt < 8; ++nt) {
                int col = h * 64 + nt * 8 + c * 2;
                float v0 = acc[mt][nt][0] * iA;
                float v1 = acc[mt][nt][1] * iA;
                float v2 = acc[mt][nt][2] * iB;
                float v3 = acc[mt][nt][3] * iB;
                v0 = v0 > 0.f ? v0 : (ex2f(v0 * LOG2E) - 1.f);
                v1 = v1 > 0.f ? v1 : (ex2f(v1 * LOG2E) - 1.f);
                v2 = v2 > 0.f ? v2 : (ex2f(v2 * LOG2E) - 1.f);
                v3 = v3 > 0.f ? v3 : (ex2f(v3 * LOG2E) - 1.f);
                *(__nv_bfloat162*)(outB + (size_t)rA * FCAT + col) =
                    __floats2bfloat162_rn(v0, v1);
                *(__nv_bfloat162*)(outB + (size_t)(rA + 8) * FCAT + col) =
                    __floats2bfloat162_rn(v2, v3);
            }
        }
    } else {
#pragma unroll
        for (int mt = 0; mt < 2; ++mt) {
            int rA = i0 + w * 32 + mt * 16 + r;
            float* pA = part + ((size_t)blockIdx.z * GN + rA) * 72;
            float* pB = pA + 8 * 72;
#pragma unroll
            for (int nt = 0; nt < 8; ++nt) {
                int col = nt * 8 + c * 2;
                *(float2*)(pA + col) = make_float2(acc[mt][nt][0], acc[mt][nt][1]);
                *(float2*)(pB + col) = make_float2(acc[mt][nt][2], acc[mt][nt][3]);
            }
            if (c == 0) { pA[64] = acc[mt][8][0]; pB[64] = acc[mt][8][2]; }
        }
    }
}

// ---------------- reduce partials + ELU + log_softmax ----------------
__global__ void reduce_lsm_kernel(const float* __restrict__ part,
                                  float* __restrict__ out) {
    int row = blockIdx.x * 8 + (threadIdx.x >> 5);
    int ln  = threadIdx.x & 31;
    float n0 = 0.f, n1 = 0.f, d = 0.f;
#pragma unroll
    for (int js = 0; js < JS2; ++js) {
        const float* b = part + ((size_t)js * GN + row) * 72;
        n0 += b[ln]; n1 += b[ln + 32]; d += b[64];
    }
    float inv = 1.f / d;
    float v0 = n0 * inv, v1 = n1 * inv;
    v0 = v0 > 0.f ? v0 : (__expf(v0) - 1.f);
    v1 = v1 > 0.f ? v1 : (__expf(v1) - 1.f);
    float mx = fmaxf(v0, v1);
#pragma unroll
    for (int o = 16; o; o >>= 1) mx = fmaxf(mx, __shfl_xor_sync(0xffffffffu, mx, o));
    float s = __expf(v0 - mx) + __expf(v1 - mx);
#pragma unroll
    for (int o = 16; o; o >>= 1) s += __shfl_xor_sync(0xffffffffu, s, o);
    float l = mx + __logf(s);
    out[(size_t)row * 64 + ln]      = v0 - l;
    out[(size_t)row * 64 + ln + 32] = v1 - l;
}

// ---------------- launch ----------------
extern "C" void kernel_launch(void* const* d_in, const int* in_sizes, int n_in,
                              void* d_out, int out_size) {
    const float* x   = (const float*)d_in[0];
    const int*   adj = (const int*)d_in[1];
    const float* W   = (const float*)d_in[2];
    const float* a1  = (const float*)d_in[3];
    const float* a2  = (const float*)d_in[4];
    const float* W2  = (const float*)d_in[5];
    const float* a21 = (const float*)d_in[6];
    const float* a22 = (const float*)d_in[7];
    float* out = (float*)d_out;

    uint32_t* adjbits; unsigned* gmaxi;
    float *wh1, *s1, *s2, *wh2, *s21, *s22, *part;
    __nv_bfloat16 *xb, *Wb, *W2b, *whTb, *hbufb, *whT2b;
    cudaGetSymbolAddress((void**)&adjbits, g_adjbits);
    cudaGetSymbolAddress((void**)&gmaxi, g_gmaxi);
    cudaGetSymbolAddress((void**)&xb,    g_xb);
    cudaGetSymbolAddress((void**)&Wb,    g_Wb);
    cudaGetSymbolAddress((void**)&W2b,   g_W2b);
    cudaGetSymbolAddress((void**)&wh1,   g_wh1);
    cudaGetSymbolAddress((void**)&whTb,  g_whTb);
    cudaGetSymbolAddress((void**)&s1,    g_s1);
    cudaGetSymbolAddress((void**)&s2,    g_s2);
    cudaGetSymbolAddress((void**)&hbufb, g_hbufb);
    cudaGetSymbolAddress((void**)&wh2,   g_wh2);
    cudaGetSymbolAddress((void**)&whT2b, g_whT2b);
    cudaGetSymbolAddress((void**)&s21,   g_s21);
    cudaGetSymbolAddress((void**)&s22,   g_s22);
    cudaGetSymbolAddress((void**)&part,  g_part);

    pack_adj_kernel<<<(GN * GN) / 256, 256>>>(adj, adjbits, gmaxi);
    cvt_bf16_kernel<<<(GN * FCAT) / 512, 256>>>(x, xb);
    cvt_bf16_kernel<<<(FCAT * FCAT) / 512, 256>>>(W, Wb);
    cvt_bf16_kernel<<<(HIDF * FCAT) / 512, 256>>>(W2, W2b);
    gemm_bf16_nt<<<dim3(FCAT / 64, GN / 128), 256>>>(xb, Wb, wh1, FCAT, FCAT);
    scores_kernel<<<(GN * GH) / 8, 256>>>(wh1, FCAT, GH, a1, a2, s1, s2, gmaxi);
    transpose_cvt_kernel<<<dim3(FCAT / 32, GN / 32), dim3(32, 8)>>>(wh1, whTb, FCAT);
    attn_mma_kernel<1><<<dim3(GN / 128, GH, 1), 128>>>(whTb, s1, s2, gmaxi,
                                                       adjbits, nullptr, hbufb);
    gemm_bf16_nt<<<dim3(1, GN / 128), 256>>>(hbufb, W2b, wh2, FCAT, HIDF);
    scores_kernel<<<GN / 8, 256>>>(wh2, HIDF, 1, a21, a22, s21, s22, gmaxi + 8);
    transpose_cvt_kernel<<<dim3(HIDF / 32, GN / 32), dim3(32, 8)>>>(wh2, whT2b, HIDF);
    attn_mma_kernel<JS2><<<dim3(GN / 128, 1, JS2), 128>>>(whT2b, s21, s22, gmaxi + 8,
                                                          adjbits, part, nullptr);
    reduce_lsm_kernel<<<GN / 8, 256>>>(part, out);
}

// round 6
// speedup vs baseline: 10.5711x; 1.1841x over previous
#include <cuda_runtime.h>
#include <cuda_bf16.h>
#include <stdint.h>

#define GN 4096
#define GH 8
#define FCAT 512
#define HIDF 64
#define ADJW (GN/32)
#define JS1 2
#define JS2 16
#define LOG2E 1.4426950408889634f

// ---------------- scratch ----------------
__device__ uint32_t      g_adjbits[GN * ADJW];
__device__ __nv_bfloat16 g_xb[GN * FCAT];
__device__ __nv_bfloat16 g_Wb[FCAT * FCAT];
__device__ __nv_bfloat16 g_W2b[HIDF * FCAT];
__device__ float         g_wh1[GN * FCAT];
__device__ __nv_bfloat16 g_whTb[FCAT * GN];
__device__ float         g_s1[GH * GN];
__device__ float         g_s2[GH * GN];
__device__ unsigned      g_gmaxi[16];
__device__ __nv_bfloat16 g_hbufb[GN * FCAT];
__device__ float         g_wh2[GN * HIDF];
__device__ __nv_bfloat16 g_whT2b[HIDF * GN];
__device__ float         g_s21[GN];
__device__ float         g_s22[GN];
__device__ float         g_part[16 * GN * 72];    // 16 slots x [row][72]

__device__ __forceinline__ unsigned fenc(float f) {
    unsigned b = __float_as_uint(f);
    return (b & 0x80000000u) ? ~b : (b | 0x80000000u);
}
__device__ __forceinline__ float fdec(unsigned k) {
    return __uint_as_float((k & 0x80000000u) ? (k & 0x7fffffffu) : ~k);
}
__device__ __forceinline__ float ex2f(float x) {
    float y; asm("ex2.approx.f32 %0, %1;" : "=f"(y) : "f"(x)); return y;
}
__device__ __forceinline__ uint32_t sptr(const void* p) {
    return (uint32_t)__cvta_generic_to_shared(p);
}
__device__ __forceinline__ void ldsm4(uint32_t* r, uint32_t a) {
    asm volatile("ldmatrix.sync.aligned.m8n8.x4.shared.b16 {%0,%1,%2,%3}, [%4];"
                 : "=r"(r[0]), "=r"(r[1]), "=r"(r[2]), "=r"(r[3]) : "r"(a));
}
__device__ __forceinline__ void ldsm2(uint32_t* r, uint32_t a) {
    asm volatile("ldmatrix.sync.aligned.m8n8.x2.shared.b16 {%0,%1}, [%2];"
                 : "=r"(r[0]), "=r"(r[1]) : "r"(a));
}
__device__ __forceinline__ void cpa16(uint32_t dst, const void* src) {
    asm volatile("cp.async.cg.shared.global [%0], [%1], 16;" :: "r"(dst), "l"(src));
}
__device__ __forceinline__ void cpa_commit() {
    asm volatile("cp.async.commit_group;");
}
template<int N>
__device__ __forceinline__ void cpa_wait() {
    asm volatile("cp.async.wait_group %0;" :: "n"(N));
}
__device__ __forceinline__ void mma16816(float* d, const uint32_t* a,
                                         uint32_t b0, uint32_t b1) {
    asm volatile(
        "mma.sync.aligned.m16n8k16.row.col.f32.bf16.bf16.f32 "
        "{%0,%1,%2,%3}, {%4,%5,%6,%7}, {%8,%9}, {%0,%1,%2,%3};"
        : "+f"(d[0]), "+f"(d[1]), "+f"(d[2]), "+f"(d[3])
        : "r"(a[0]), "r"(a[1]), "r"(a[2]), "r"(a[3]), "r"(b0), "r"(b1));
}

// ---------------- pack adjacency (4x unrolled) + init gmax ----------------
__global__ void pack_adj_kernel(const int* __restrict__ adj,
                                uint32_t* __restrict__ bits,
                                unsigned* __restrict__ gmaxi) {
    if (blockIdx.x == 0 && threadIdx.x < 16) gmaxi[threadIdx.x] = 0u;
    int wg   = (blockIdx.x * 256 + threadIdx.x) >> 5;   // global warp id
    int lane = threadIdx.x & 31;
    int base = wg * 128;
    int v0 = adj[base + lane];
    int v1 = adj[base + 32 + lane];
    int v2 = adj[base + 64 + lane];
    int v3 = adj[base + 96 + lane];
    uint32_t b[4];
    b[0] = __ballot_sync(0xffffffffu, v0 > 0);
    b[1] = __ballot_sync(0xffffffffu, v1 > 0);
    b[2] = __ballot_sync(0xffffffffu, v2 > 0);
    b[3] = __ballot_sync(0xffffffffu, v3 > 0);
    if (lane < 4) bits[wg * 4 + lane] = b[lane];
}

// ---------------- fp32 -> bf16 elementwise ----------------
__global__ void cvt_bf16_kernel(const float* __restrict__ in,
                                __nv_bfloat16* __restrict__ out) {
    int id = (blockIdx.x * 256 + threadIdx.x) * 2;
    float2 v = *(const float2*)(in + id);
    *(__nv_bfloat162*)(out + id) = __floats2bfloat162_rn(v.x, v.y);
}

// ---------------- fp32 [GN][C] -> bf16 transposed [C][GN] ----------------
__global__ void transpose_cvt_kernel(const float* __restrict__ in,
                                     __nv_bfloat16* __restrict__ out, int C) {
    __shared__ float tile[32][33];
    int tx = threadIdx.x, ty = threadIdx.y;
    int c0 = blockIdx.x * 32;
    int r0 = blockIdx.y * 32;
#pragma unroll
    for (int k = 0; k < 4; ++k)
        tile[ty + k * 8][tx] = in[(size_t)(r0 + ty + k * 8) * C + c0 + tx];
    __syncthreads();
#pragma unroll
    for (int k = 0; k < 4; ++k)
        out[(size_t)(c0 + ty + k * 8) * GN + r0 + tx] =
            __float2bfloat16(tile[tx][ty + k * 8]);
}

// ---------------- bf16 NT GEMM, cp.async double-buffered (Kc=32) ----------
__global__ void __launch_bounds__(256, 3)
gemm_bf16_nt(const __nv_bfloat16* __restrict__ A,
             const __nv_bfloat16* __restrict__ B,
             float* __restrict__ C, int K, int Ncols) {
    __shared__ __nv_bfloat16 As[2][128 * 40];
    __shared__ __nv_bfloat16 Bs[2][64 * 40];

    const int t  = threadIdx.x;
    const int m0 = blockIdx.y * 128;
    const int n0 = blockIdx.x * 64;
    const int w = t >> 5, ln = t & 31;
    const int r = ln >> 2, c = ln & 3;

    const uint32_t aB = sptr(As[0]) + (uint32_t)(((w * 16 + (ln & 15)) * 40 +
                                                  ((ln >> 4) & 1) * 8) * 2);
    const uint32_t bB = sptr(Bs[0]) + (uint32_t)((((ln & 7) + ((ln >> 4) & 1) * 8) * 40 +
                                                  ((ln >> 3) & 1) * 8) * 2);
    const uint32_t ABUF = 128 * 40 * 2;
    const uint32_t BBUF = 64 * 40 * 2;

    float acc[8][4];
#pragma unroll
    for (int nt = 0; nt < 8; ++nt)
#pragma unroll
        for (int q = 0; q < 4; ++q) acc[nt][q] = 0.f;

    auto g_issue = [&](int ki) {
        int buf = ki & 1;
        int kc = ki * 32;
#pragma unroll
        for (int it = 0; it < 2; ++it) {
            int idx = it * 256 + t;
            int row = idx >> 2, u = idx & 3;
            cpa16(sptr(&As[buf][row * 40 + u * 8]),
                  A + (size_t)(m0 + row) * K + kc + u * 8);
        }
        {
            int row = t >> 2, u = t & 3;
            cpa16(sptr(&Bs[buf][row * 40 + u * 8]),
                  B + (size_t)(n0 + row) * K + kc + u * 8);
        }
    };

    const int NK = K / 32;
    g_issue(0); cpa_commit();
    for (int ki = 0; ki < NK; ++ki) {
        if (ki + 1 < NK) { g_issue(ki + 1); cpa_commit(); cpa_wait<1>(); }
        else             { cpa_wait<0>(); }
        __syncthreads();
        const int buf = ki & 1;
#pragma unroll
        for (int kt = 0; kt < 2; ++kt) {
            uint32_t a[4];
            ldsm4(a, aB + buf * ABUF + kt * 32);
#pragma unroll
            for (int p = 0; p < 4; ++p) {
                uint32_t b[4];
                // 16 n-rows per p step: 16 * 40 bf16 * 2B = 1280 bytes
                ldsm4(b, bB + buf * BBUF + p * 1280 + kt * 32);
                mma16816(acc[2 * p],     a, b[0], b[1]);
                mma16816(acc[2 * p + 1], a, b[2], b[3]);
            }
        }
        __syncthreads();
    }
    int rA = m0 + w * 16 + r;
#pragma unroll
    for (int nt = 0; nt < 8; ++nt) {
        int col = n0 + nt * 8 + c * 2;
        *(float2*)&C[(size_t)rA * Ncols + col]       = make_float2(acc[nt][0], acc[nt][1]);
        *(float2*)&C[(size_t)(rA + 8) * Ncols + col] = make_float2(acc[nt][2], acc[nt][3]);
    }
}

// ---------------- scores (pre-scaled by log2e) + fused global max ----------
__global__ void scores_kernel(const float* __restrict__ wh, int stride, int nH,
                              const float* __restrict__ a1, const float* __restrict__ a2,
                              float* __restrict__ s1, float* __restrict__ s2,
                              unsigned* __restrict__ gmaxi) {
    int w    = blockIdx.x * 8 + (threadIdx.x >> 5);
    int lane = threadIdx.x & 31;
    int i = w / nH, h = w % nH;
    const float* base = wh + (size_t)i * stride + h * 64;
    float v0 = base[lane], v1 = base[lane + 32];
    float p1 = v0 * a1[h * 64 + lane] + v1 * a1[h * 64 + lane + 32];
    float p2 = v0 * a2[h * 64 + lane] + v1 * a2[h * 64 + lane + 32];
#pragma unroll
    for (int o = 16; o; o >>= 1) {
        p1 += __shfl_down_sync(0xffffffffu, p1, o);
        p2 += __shfl_down_sync(0xffffffffu, p2, o);
    }
    if (lane == 0) {
        p1 *= LOG2E; p2 *= LOG2E;
        s1[h * GN + i] = p1;
        s2[h * GN + i] = p2;
        atomicMax(&gmaxi[h], fenc(p2));
    }
}

// ---------------- fused masked softmax + att@wh (256 thr, 8 warps) --------
// TI=128 rows/block; warp w owns m-tile w (16 rows). phase-1: 2 thr/row, one
// adj word each. j-split JS across blockIdx.z; partials (num[64], den) out.
template<int JS>
__global__ void __launch_bounds__(256, 3)
attn_mma_kernel(const __nv_bfloat16* __restrict__ whT,
                const float* __restrict__ s1g, const float* __restrict__ s2g,
                const unsigned* __restrict__ gmaxi,
                const uint32_t* __restrict__ adjbits,
                float* __restrict__ part) {
    __shared__ __nv_bfloat16 ps[128 * 72];
    __shared__ __nv_bfloat16 whs[2][72 * 72];
    __shared__ float s2t[2][64];

    const int t  = threadIdx.x;
    const int i0 = blockIdx.x * 128;
    const int h  = blockIdx.y;
    const int jbase = blockIdx.z * (GN / JS);
    const int NT = (GN / JS) / 64;

    const __nv_bfloat16* whTh = whT + (size_t)h * 64 * GN;
    const float* s2h = s2g + h * GN;
    uint32_t* psW = reinterpret_cast<uint32_t*>(ps);

    // constant rows 64..71 of both whs buffers (row 64 = ones -> den column)
#pragma unroll
    for (int b = 0; b < 2; ++b)
        for (int idx = t; idx < 8 * 36; idx += 256) {
            int rr = idx / 36, wd = idx - rr * 36;
            reinterpret_cast<uint32_t*>(whs[b])[(64 + rr) * 36 + wd] =
                (rr == 0) ? 0x3F803F80u : 0u;
        }

    auto issue_tile = [&](int tt) {
        int buf = tt & 1;
        int j0 = jbase + tt * 64;
#pragma unroll
        for (int it = 0; it < 2; ++it) {
            int idx = it * 256 + t;
            int f = idx >> 3, u = idx & 7;
            cpa16(sptr(&whs[buf][f * 72 + u * 8]), whTh + (size_t)f * GN + j0 + u * 8);
        }
        if (t < 16) cpa16(sptr(&s2t[buf][t * 4]), s2h + j0 + t * 4);
    };

    issue_tile(0);
    cpa_commit();

    const int rt = t >> 1, jh = t & 1;          // phase-1: row / adj-word half
    const float s1i = s1g[h * GN + i0 + rt];
    const float gme = s1i + fdec(gmaxi[h]);
    const float m = fmaxf(gme, 0.2f * gme);

    const int w = t >> 5, ln = t & 31;
    const int r = ln >> 2, c = ln & 3;

    const uint32_t psB = sptr(ps) + (uint32_t)(((w * 16 + (ln & 15)) * 72 +
                                                ((ln >> 4) & 1) * 8) * 2);
    const uint32_t whB0 = sptr(whs[0]) + (uint32_t)((((ln & 7) + ((ln >> 4) & 1) * 8) * 72 +
                                                     ((ln >> 3) & 1) * 8) * 2);
    const uint32_t dnB0 = sptr(whs[0]) + (uint32_t)(((64 + (ln & 7)) * 72 +
                                                     ((ln >> 3) & 1) * 8) * 2);
    const uint32_t bufStride = (uint32_t)(72 * 72 * 2);

    float acc[9][4];
#pragma unroll
    for (int nt = 0; nt < 9; ++nt)
#pragma unroll
        for (int q = 0; q < 4; ++q) acc[nt][q] = 0.f;

    const uint32_t* adjRow = adjbits + (size_t)(i0 + rt) * ADJW;

    for (int tt = 0; tt < NT; ++tt) {
        if (tt + 1 < NT) { issue_tile(tt + 1); cpa_commit(); cpa_wait<1>(); }
        else             { cpa_wait<0>(); }
        __syncthreads();

        const int buf = tt & 1;
        const int j0  = jbase + tt * 64;

        // ---- phase 1: 32 p's (row rt, adj word jh) ----
        const uint32_t wv = adjRow[(j0 >> 5) + jh];
        const float2* s2p = reinterpret_cast<const float2*>(s2t[buf] + jh * 32);
#pragma unroll
        for (int u = 0; u < 4; ++u) {
            uint32_t pk[4];
#pragma unroll
            for (int q = 0; q < 4; ++q) {
                int j = u * 8 + q * 2;                     // 0..30 within word
                float2 sv = s2p[u * 4 + q];
                float e0 = s1i + sv.x, e1 = s1i + sv.y;
                float a0 = fmaxf(e0, 0.2f * e0) - m;
                float a1 = fmaxf(e1, 0.2f * e1) - m;
                float p0 = ((wv >> j) & 1u)       ? ex2f(a0) : 0.f;
                float p1 = ((wv >> (j + 1)) & 1u) ? ex2f(a1) : 0.f;
                __nv_bfloat162 h2 = __floats2bfloat162_rn(p0, p1);
                pk[q] = *reinterpret_cast<uint32_t*>(&h2);
            }
            *(uint4*)(psW + rt * 36 + jh * 16 + u * 4) =
                make_uint4(pk[0], pk[1], pk[2], pk[3]);
        }
        __syncthreads();

        // ---- phase 2: warp w -> m-tile w, all 9 n-tiles ----
        const uint32_t whB = whB0 + buf * bufStride;
        const uint32_t dnB = dnB0 + buf * bufStride;
#pragma unroll
        for (int kt = 0; kt < 4; ++kt) {
            uint32_t a[4];
            ldsm4(a, psB + kt * 32);
#pragma unroll
            for (int p = 0; p < 4; ++p) {
                uint32_t b[4];
                ldsm4(b, whB + p * 2304 + kt * 32);
                mma16816(acc[2 * p],     a, b[0], b[1]);
                mma16816(acc[2 * p + 1], a, b[2], b[3]);
            }
            uint32_t d[2];
            ldsm2(d, dnB + kt * 32);
            mma16816(acc[8], a, d[0], d[1]);
        }
        __syncthreads();
    }

    // ---- store partials: slot = h*JS + z ----
    int rA = i0 + w * 16 + r;
    float* pA = part + (((size_t)(h * JS + blockIdx.z)) * GN + rA) * 72;
    float* pB = pA + 8 * 72;
#pragma unroll
    for (int nt = 0; nt < 8; ++nt) {
        int col = nt * 8 + c * 2;
        *(float2*)(pA + col) = make_float2(acc[nt][0], acc[nt][1]);
        *(float2*)(pB + col) = make_float2(acc[nt][2], acc[nt][3]);
    }
    if (c == 0) { pA[64] = acc[8][0]; pB[64] = acc[8][2]; }
}

// ---------------- layer-1 reduce: sum JS1 partials, ELU, bf16 store --------
__global__ void reduce_hbuf_kernel(const float* __restrict__ part,
                                   __nv_bfloat16* __restrict__ outB) {
    int id  = blockIdx.x * 256 + threadIdx.x;   // over GN*256 (2 cols each)
    int row = id >> 8;
    int cp  = (id & 255) * 2;                    // 0..510
    int h   = cp >> 6;
    int cl  = cp & 63;
    const float* r0 = part + (((size_t)(h * JS1 + 0)) * GN + row) * 72;
    const float* r1 = part + (((size_t)(h * JS1 + 1)) * GN + row) * 72;
    float2 n0 = *(const float2*)(r0 + cl);
    float2 n1 = *(const float2*)(r1 + cl);
    float inv = 1.f / (r0[64] + r1[64]);
    float v0 = (n0.x + n1.x) * inv;
    float v1 = (n0.y + n1.y) * inv;
    v0 = v0 > 0.f ? v0 : (ex2f(v0 * LOG2E) - 1.f);
    v1 = v1 > 0.f ? v1 : (ex2f(v1 * LOG2E) - 1.f);
    *(__nv_bfloat162*)(outB + (size_t)row * FCAT + cp) = __floats2bfloat162_rn(v0, v1);
}

// ---------------- layer-2 reduce: sum JS2 partials + ELU + log_softmax ----
__global__ void reduce_lsm_kernel(const float* __restrict__ part,
                                  float* __restrict__ out) {
    int row = blockIdx.x * 8 + (threadIdx.x >> 5);
    int ln  = threadIdx.x & 31;
    float n0 = 0.f, n1 = 0.f, d = 0.f;
#pragma unroll
    for (int js = 0; js < JS2; ++js) {
        const float* b = part + ((size_t)js * GN + row) * 72;
        n0 += b[ln]; n1 += b[ln + 32]; d += b[64];
    }
    float inv = 1.f / d;
    float v0 = n0 * inv, v1 = n1 * inv;
    v0 = v0 > 0.f ? v0 : (__expf(v0) - 1.f);
    v1 = v1 > 0.f ? v1 : (__expf(v1) - 1.f);
    float mx = fmaxf(v0, v1);
#pragma unroll
    for (int o = 16; o; o >>= 1) mx = fmaxf(mx, __shfl_xor_sync(0xffffffffu, mx, o));
    float s = __expf(v0 - mx) + __expf(v1 - mx);
#pragma unroll
    for (int o = 16; o; o >>= 1) s += __shfl_xor_sync(0xffffffffu, s, o);
    float l = mx + __logf(s);
    out[(size_t)row * 64 + ln]      = v0 - l;
    out[(size_t)row * 64 + ln + 32] = v1 - l;
}

// ---------------- launch ----------------
extern "C" void kernel_launch(void* const* d_in, const int* in_sizes, int n_in,
                              void* d_out, int out_size) {
    const float* x   = (const float*)d_in[0];
    const int*   adj = (const int*)d_in[1];
    const float* W   = (const float*)d_in[2];
    const float* a1  = (const float*)d_in[3];
    const float* a2  = (const float*)d_in[4];
    const float* W2  = (const float*)d_in[5];
    const float* a21 = (const float*)d_in[6];
    const float* a22 = (const float*)d_in[7];
    float* out = (float*)d_out;

    uint32_t* adjbits; unsigned* gmaxi;
    float *wh1, *s1, *s2, *wh2, *s21, *s22, *part;
    __nv_bfloat16 *xb, *Wb, *W2b, *whTb, *hbufb, *whT2b;
    cudaGetSymbolAddress((void**)&adjbits, g_adjbits);
    cudaGetSymbolAddress((void**)&gmaxi, g_gmaxi);
    cudaGetSymbolAddress((void**)&xb,    g_xb);
    cudaGetSymbolAddress((void**)&Wb,    g_Wb);
    cudaGetSymbolAddress((void**)&W2b,   g_W2b);
    cudaGetSymbolAddress((void**)&wh1,   g_wh1);
    cudaGetSymbolAddress((void**)&whTb,  g_whTb);
    cudaGetSymbolAddress((void**)&s1,    g_s1);
    cudaGetSymbolAddress((void**)&s2,    g_s2);
    cudaGetSymbolAddress((void**)&hbufb, g_hbufb);
    cudaGetSymbolAddress((void**)&wh2,   g_wh2);
    cudaGetSymbolAddress((void**)&whT2b, g_whT2b);
    cudaGetSymbolAddress((void**)&s21,   g_s21);
    cudaGetSymbolAddress((void**)&s22,   g_s22);
    cudaGetSymbolAddress((void**)&part,  g_part);

    pack_adj_kernel<<<(GN * GN) / 1024, 256>>>(adj, adjbits, gmaxi);
    cvt_bf16_kernel<<<(GN * FCAT) / 512, 256>>>(x, xb);
    cvt_bf16_kernel<<<(FCAT * FCAT) / 512, 256>>>(W, Wb);
    cvt_bf16_kernel<<<(HIDF * FCAT) / 512, 256>>>(W2, W2b);
    gemm_bf16_nt<<<dim3(FCAT / 64, GN / 128), 256>>>(xb, Wb, wh1, FCAT, FCAT);
    scores_kernel<<<(GN * GH) / 8, 256>>>(wh1, FCAT, GH, a1, a2, s1, s2, gmaxi);
    transpose_cvt_kernel<<<dim3(FCAT / 32, GN / 32), dim3(32, 8)>>>(wh1, whTb, FCAT);
    attn_mma_kernel<JS1><<<dim3(GN / 128, GH, JS1), 256>>>(whTb, s1, s2, gmaxi,
                                                           adjbits, part);
    reduce_hbuf_kernel<<<GN, 256>>>(part, hbufb);
    gemm_bf16_nt<<<dim3(1, GN / 128), 256>>>(hbufb, W2b, wh2, FCAT, HIDF);
    scores_kernel<<<GN / 8, 256>>>(wh2, HIDF, 1, a21, a22, s21, s22, gmaxi + 8);
    transpose_cvt_kernel<<<dim3(HIDF / 32, GN / 32), dim3(32, 8)>>>(wh2, whT2b, HIDF);
    attn_mma_kernel<JS2><<<dim3(GN / 128, 1, JS2), 256>>>(whT2b, s21, s22, gmaxi + 8,
                                                          adjbits, part);
    reduce_lsm_kernel<<<GN / 8, 256>>>(part, out);
}

// round 7
// speedup vs baseline: 10.6564x; 1.0081x over previous
#include <cuda_runtime.h>
#include <cuda_bf16.h>
#include <stdint.h>

#define GN 4096
#define GH 8
#define FCAT 512
#define HIDF 64
#define ADJW (GN/32)
#define JS1 2
#define JS2 16
#define LOG2E 1.4426950408889634f

// ---------------- scratch ----------------
__device__ uint32_t      g_adjbits[GN * ADJW];
__device__ __nv_bfloat16 g_xb[GN * FCAT];
__device__ __nv_bfloat16 g_Wb[FCAT * FCAT];
__device__ __nv_bfloat16 g_W2b[HIDF * FCAT];
__device__ float         g_wh1[GN * FCAT];
__device__ __nv_bfloat16 g_whTb[FCAT * GN];
__device__ float         g_s1[GH * GN];
__device__ float         g_s2[GH * GN];
__device__ float         g_e2[GH * GN];     // ex2(s2)
__device__ float         g_e2b[GH * GN];    // ex2(0.2*s2)
__device__ unsigned      g_gmaxi[16];
__device__ __nv_bfloat16 g_hbufb[GN * FCAT];
__device__ float         g_wh2[GN * HIDF];
__device__ __nv_bfloat16 g_whT2b[HIDF * GN];
__device__ float         g_s21[GN];
__device__ float         g_s22[GN];
__device__ float         g_e22[GN];
__device__ float         g_e22b[GN];
__device__ float         g_part[16 * GN * 72];    // 16 slots x [row][72]

__device__ __forceinline__ unsigned fenc(float f) {
    unsigned b = __float_as_uint(f);
    return (b & 0x80000000u) ? ~b : (b | 0x80000000u);
}
__device__ __forceinline__ float fdec(unsigned k) {
    return __uint_as_float((k & 0x80000000u) ? (k & 0x7fffffffu) : ~k);
}
__device__ __forceinline__ float ex2f(float x) {
    float y; asm("ex2.approx.f32 %0, %1;" : "=f"(y) : "f"(x)); return y;
}
__device__ __forceinline__ uint32_t sptr(const void* p) {
    return (uint32_t)__cvta_generic_to_shared(p);
}
__device__ __forceinline__ void ldsm4(uint32_t* r, uint32_t a) {
    asm volatile("ldmatrix.sync.aligned.m8n8.x4.shared.b16 {%0,%1,%2,%3}, [%4];"
                 : "=r"(r[0]), "=r"(r[1]), "=r"(r[2]), "=r"(r[3]) : "r"(a));
}
__device__ __forceinline__ void ldsm2(uint32_t* r, uint32_t a) {
    asm volatile("ldmatrix.sync.aligned.m8n8.x2.shared.b16 {%0,%1}, [%2];"
                 : "=r"(r[0]), "=r"(r[1]) : "r"(a));
}
__device__ __forceinline__ void cpa16(uint32_t dst, const void* src) {
    asm volatile("cp.async.cg.shared.global [%0], [%1], 16;" :: "r"(dst), "l"(src));
}
__device__ __forceinline__ void cpa_commit() {
    asm volatile("cp.async.commit_group;");
}
template<int N>
__device__ __forceinline__ void cpa_wait() {
    asm volatile("cp.async.wait_group %0;" :: "n"(N));
}
__device__ __forceinline__ void mma16816(float* d, const uint32_t* a,
                                         uint32_t b0, uint32_t b1) {
    asm volatile(
        "mma.sync.aligned.m16n8k16.row.col.f32.bf16.bf16.f32 "
        "{%0,%1,%2,%3}, {%4,%5,%6,%7}, {%8,%9}, {%0,%1,%2,%3};"
        : "+f"(d[0]), "+f"(d[1]), "+f"(d[2]), "+f"(d[3])
        : "r"(a[0]), "r"(a[1]), "r"(a[2]), "r"(a[3]), "r"(b0), "r"(b1));
}

// ---------------- pack adjacency (4x unrolled) + init gmax ----------------
__global__ void pack_adj_kernel(const int* __restrict__ adj,
                                uint32_t* __restrict__ bits,
                                unsigned* __restrict__ gmaxi) {
    if (blockIdx.x == 0 && threadIdx.x < 16) gmaxi[threadIdx.x] = 0u;
    int wg   = (blockIdx.x * 256 + threadIdx.x) >> 5;   // global warp id
    int lane = threadIdx.x & 31;
    int base = wg * 128;
    int v0 = adj[base + lane];
    int v1 = adj[base + 32 + lane];
    int v2 = adj[base + 64 + lane];
    int v3 = adj[base + 96 + lane];
    uint32_t b[4];
    b[0] = __ballot_sync(0xffffffffu, v0 > 0);
    b[1] = __ballot_sync(0xffffffffu, v1 > 0);
    b[2] = __ballot_sync(0xffffffffu, v2 > 0);
    b[3] = __ballot_sync(0xffffffffu, v3 > 0);
    if (lane < 4) bits[wg * 4 + lane] = b[lane];
}

// ---------------- fp32 -> bf16, all three inputs in one launch ------------
__global__ void cvt_all_kernel(const float* __restrict__ x, __nv_bfloat16* __restrict__ xb,
                               const float* __restrict__ W, __nv_bfloat16* __restrict__ Wb,
                               const float* __restrict__ W2, __nv_bfloat16* __restrict__ W2b) {
    const int NX = GN * FCAT / 2, NW = FCAT * FCAT / 2;
    int id = blockIdx.x * 256 + threadIdx.x;
    const float* src; __nv_bfloat16* dst; int off;
    if (id < NX)           { src = x;  dst = xb;  off = id; }
    else if (id < NX + NW) { src = W;  dst = Wb;  off = id - NX; }
    else                   { src = W2; dst = W2b; off = id - NX - NW; }
    float2 v = *(const float2*)(src + (size_t)off * 2);
    *(__nv_bfloat162*)(dst + (size_t)off * 2) = __floats2bfloat162_rn(v.x, v.y);
}

// ---------------- fp32 [GN][C] -> bf16 transposed [C][GN] ----------------
__global__ void transpose_cvt_kernel(const float* __restrict__ in,
                                     __nv_bfloat16* __restrict__ out, int C) {
    __shared__ float tile[32][33];
    int tx = threadIdx.x, ty = threadIdx.y;
    int c0 = blockIdx.x * 32;
    int r0 = blockIdx.y * 32;
#pragma unroll
    for (int k = 0; k < 4; ++k)
        tile[ty + k * 8][tx] = in[(size_t)(r0 + ty + k * 8) * C + c0 + tx];
    __syncthreads();
#pragma unroll
    for (int k = 0; k < 4; ++k)
        out[(size_t)(c0 + ty + k * 8) * GN + r0 + tx] =
            __float2bfloat16(tile[tx][ty + k * 8]);
}

// ---------------- bf16 NT GEMM, cp.async double-buffered (Kc=32) ----------
__global__ void __launch_bounds__(256, 3)
gemm_bf16_nt(const __nv_bfloat16* __restrict__ A,
             const __nv_bfloat16* __restrict__ B,
             float* __restrict__ C, int K, int Ncols) {
    __shared__ __nv_bfloat16 As[2][128 * 40];
    __shared__ __nv_bfloat16 Bs[2][64 * 40];

    const int t  = threadIdx.x;
    const int m0 = blockIdx.y * 128;
    const int n0 = blockIdx.x * 64;
    const int w = t >> 5, ln = t & 31;
    const int r = ln >> 2, c = ln & 3;

    const uint32_t aB = sptr(As[0]) + (uint32_t)(((w * 16 + (ln & 15)) * 40 +
                                                  ((ln >> 4) & 1) * 8) * 2);
    const uint32_t bB = sptr(Bs[0]) + (uint32_t)((((ln & 7) + ((ln >> 4) & 1) * 8) * 40 +
                                                  ((ln >> 3) & 1) * 8) * 2);
    const uint32_t ABUF = 128 * 40 * 2;
    const uint32_t BBUF = 64 * 40 * 2;

    float acc[8][4];
#pragma unroll
    for (int nt = 0; nt < 8; ++nt)
#pragma unroll
        for (int q = 0; q < 4; ++q) acc[nt][q] = 0.f;

    auto g_issue = [&](int ki) {
        int buf = ki & 1;
        int kc = ki * 32;
#pragma unroll
        for (int it = 0; it < 2; ++it) {
            int idx = it * 256 + t;
            int row = idx >> 2, u = idx & 3;
            cpa16(sptr(&As[buf][row * 40 + u * 8]),
                  A + (size_t)(m0 + row) * K + kc + u * 8);
        }
        {
            int row = t >> 2, u = t & 3;
            cpa16(sptr(&Bs[buf][row * 40 + u * 8]),
                  B + (size_t)(n0 + row) * K + kc + u * 8);
        }
    };

    const int NK = K / 32;
    g_issue(0); cpa_commit();
    for (int ki = 0; ki < NK; ++ki) {
        if (ki + 1 < NK) { g_issue(ki + 1); cpa_commit(); cpa_wait<1>(); }
        else             { cpa_wait<0>(); }
        __syncthreads();
        const int buf = ki & 1;
#pragma unroll
        for (int kt = 0; kt < 2; ++kt) {
            uint32_t a[4];
            ldsm4(a, aB + buf * ABUF + kt * 32);
#pragma unroll
            for (int p = 0; p < 4; ++p) {
                uint32_t b[4];
                // 16 n-rows per p step: 16 * 40 bf16 * 2B = 1280 bytes
                ldsm4(b, bB + buf * BBUF + p * 1280 + kt * 32);
                mma16816(acc[2 * p],     a, b[0], b[1]);
                mma16816(acc[2 * p + 1], a, b[2], b[3]);
            }
        }
        __syncthreads();
    }
    int rA = m0 + w * 16 + r;
#pragma unroll
    for (int nt = 0; nt < 8; ++nt) {
        int col = n0 + nt * 8 + c * 2;
        *(float2*)&C[(size_t)rA * Ncols + col]       = make_float2(acc[nt][0], acc[nt][1]);
        *(float2*)&C[(size_t)(rA + 8) * Ncols + col] = make_float2(acc[nt][2], acc[nt][3]);
    }
}

// ---------------- scores (pre-scaled by log2e) + E2 tables + global max ----
__global__ void scores_kernel(const float* __restrict__ wh, int stride, int nH,
                              const float* __restrict__ a1, const float* __restrict__ a2,
                              float* __restrict__ s1, float* __restrict__ s2,
                              float* __restrict__ e2, float* __restrict__ e2b,
                              unsigned* __restrict__ gmaxi) {
    int w    = blockIdx.x * 8 + (threadIdx.x >> 5);
    int lane = threadIdx.x & 31;
    int i = w / nH, h = w % nH;
    const float* base = wh + (size_t)i * stride + h * 64;
    float v0 = base[lane], v1 = base[lane + 32];
    float p1 = v0 * a1[h * 64 + lane] + v1 * a1[h * 64 + lane + 32];
    float p2 = v0 * a2[h * 64 + lane] + v1 * a2[h * 64 + lane + 32];
#pragma unroll
    for (int o = 16; o; o >>= 1) {
        p1 += __shfl_down_sync(0xffffffffu, p1, o);
        p2 += __shfl_down_sync(0xffffffffu, p2, o);
    }
    if (lane == 0) {
        p1 *= LOG2E; p2 *= LOG2E;
        s1[h * GN + i]  = p1;
        s2[h * GN + i]  = p2;
        e2[h * GN + i]  = ex2f(p2);
        e2b[h * GN + i] = ex2f(0.2f * p2);
        atomicMax(&gmaxi[h], fenc(p2));
    }
}

// ---------------- fused masked softmax + att@wh (256 thr, occ 4) ----------
// p separable in both leaky branches:
//   e>0:  p = E2[j]  * ci    (ci  = ex2(s1_i - m))
//   e<=0: p = E2b[j] * ci2   (ci2 = ex2(0.2*s1_i - m))
// No per-element MUFU. j-split JS across blockIdx.z; partials to scratch.
template<int JS>
__global__ void __launch_bounds__(256, 4)
attn_mma_kernel(const __nv_bfloat16* __restrict__ whT,
                const float* __restrict__ s1g, const float* __restrict__ s2g,
                const float* __restrict__ e2g, const float* __restrict__ e2bg,
                const unsigned* __restrict__ gmaxi,
                const uint32_t* __restrict__ adjbits,
                float* __restrict__ part) {
    __shared__ __nv_bfloat16 ps[128 * 72];
    __shared__ __nv_bfloat16 whs[2][72 * 72];
    __shared__ float s2t[2][64];
    __shared__ float e2t[2][64];
    __shared__ float e2bt[2][64];

    const int t  = threadIdx.x;
    const int i0 = blockIdx.x * 128;
    const int h  = blockIdx.y;
    const int jbase = blockIdx.z * (GN / JS);
    const int NT = (GN / JS) / 64;

    const __nv_bfloat16* whTh = whT + (size_t)h * 64 * GN;
    const float* s2h  = s2g  + h * GN;
    const float* e2h  = e2g  + h * GN;
    const float* e2bh = e2bg + h * GN;
    uint32_t* psW = reinterpret_cast<uint32_t*>(ps);

    // constant rows 64..71 of both whs buffers (row 64 = ones -> den column)
#pragma unroll
    for (int b = 0; b < 2; ++b)
        for (int idx = t; idx < 8 * 36; idx += 256) {
            int rr = idx / 36, wd = idx - rr * 36;
            reinterpret_cast<uint32_t*>(whs[b])[(64 + rr) * 36 + wd] =
                (rr == 0) ? 0x3F803F80u : 0u;
        }

    auto issue_tile = [&](int tt) {
        int buf = tt & 1;
        int j0 = jbase + tt * 64;
#pragma unroll
        for (int it = 0; it < 2; ++it) {
            int idx = it * 256 + t;
            int f = idx >> 3, u = idx & 7;
            cpa16(sptr(&whs[buf][f * 72 + u * 8]), whTh + (size_t)f * GN + j0 + u * 8);
        }
        if (t < 16)      cpa16(sptr(&s2t[buf][t * 4]),         s2h  + j0 + t * 4);
        else if (t < 32) cpa16(sptr(&e2t[buf][(t - 16) * 4]),  e2h  + j0 + (t - 16) * 4);
        else if (t < 48) cpa16(sptr(&e2bt[buf][(t - 32) * 4]), e2bh + j0 + (t - 32) * 4);
    };

    issue_tile(0);
    cpa_commit();

    const int rt = t >> 1, jh = t & 1;          // phase-1: row / adj-word half
    const float s1i = s1g[h * GN + i0 + rt];
    const float gme = s1i + fdec(gmaxi[h]);
    const float m   = fmaxf(gme, 0.2f * gme);
    const float ci  = ex2f(s1i - m);
    const float ci2 = ex2f(0.2f * s1i - m);
    const float ns1 = -s1i;

    const int w = t >> 5, ln = t & 31;
    const int r = ln >> 2, c = ln & 3;

    const uint32_t psB = sptr(ps) + (uint32_t)(((w * 16 + (ln & 15)) * 72 +
                                                ((ln >> 4) & 1) * 8) * 2);
    const uint32_t whB0 = sptr(whs[0]) + (uint32_t)((((ln & 7) + ((ln >> 4) & 1) * 8) * 72 +
                                                     ((ln >> 3) & 1) * 8) * 2);
    const uint32_t dnB0 = sptr(whs[0]) + (uint32_t)(((64 + (ln & 7)) * 72 +
                                                     ((ln >> 3) & 1) * 8) * 2);
    const uint32_t bufStride = (uint32_t)(72 * 72 * 2);

    float acc[9][4];
#pragma unroll
    for (int nt = 0; nt < 9; ++nt)
#pragma unroll
        for (int q = 0; q < 4; ++q) acc[nt][q] = 0.f;

    const uint32_t* adjRow = adjbits + (size_t)(i0 + rt) * ADJW;

    for (int tt = 0; tt < NT; ++tt) {
        if (tt + 1 < NT) { issue_tile(tt + 1); cpa_commit(); cpa_wait<1>(); }
        else             { cpa_wait<0>(); }
        __syncthreads();

        const int buf = tt & 1;
        const int j0  = jbase + tt * 64;

        // ---- phase 1: 32 p's (row rt, adj word jh), no MUFU ----
        const uint32_t wv = adjRow[(j0 >> 5) + jh];
        const float2* s2p  = reinterpret_cast<const float2*>(s2t[buf]  + jh * 32);
        const float2* e2p  = reinterpret_cast<const float2*>(e2t[buf]  + jh * 32);
        const float2* e2bp = reinterpret_cast<const float2*>(e2bt[buf] + jh * 32);
#pragma unroll
        for (int u = 0; u < 4; ++u) {
            uint32_t pk[4];
#pragma unroll
            for (int q = 0; q < 4; ++q) {
                int j = u * 8 + q * 2;                     // 0..30 within word
                float2 sv = s2p[u * 4 + q];
                float2 ev = e2p[u * 4 + q];
                float2 bv = e2bp[u * 4 + q];
                float p0 = (sv.x > ns1) ? ev.x * ci : bv.x * ci2;
                float p1 = (sv.y > ns1) ? ev.y * ci : bv.y * ci2;
                p0 = ((wv >> j) & 1u)       ? p0 : 0.f;
                p1 = ((wv >> (j + 1)) & 1u) ? p1 : 0.f;
                __nv_bfloat162 h2 = __floats2bfloat162_rn(p0, p1);
                pk[q] = *reinterpret_cast<uint32_t*>(&h2);
            }
            *(uint4*)(psW + rt * 36 + jh * 16 + u * 4) =
                make_uint4(pk[0], pk[1], pk[2], pk[3]);
        }
        __syncthreads();

        // ---- phase 2: warp w -> m-tile w, all 9 n-tiles ----
        const uint32_t whB = whB0 + buf * bufStride;
        const uint32_t dnB = dnB0 + buf * bufStride;
#pragma unroll
        for (int kt = 0; kt < 4; ++kt) {
            uint32_t a[4];
            ldsm4(a, psB + kt * 32);
#pragma unroll
            for (int p = 0; p < 4; ++p) {
                uint32_t b[4];
                ldsm4(b, whB + p * 2304 + kt * 32);
                mma16816(acc[2 * p],     a, b[0], b[1]);
                mma16816(acc[2 * p + 1], a, b[2], b[3]);
            }
            uint32_t d[2];
            ldsm2(d, dnB + kt * 32);
            mma16816(acc[8], a, d[0], d[1]);
        }
        __syncthreads();
    }

    // ---- store partials: slot = h*JS + z ----
    int rA = i0 + w * 16 + r;
    float* pA = part + (((size_t)(h * JS + blockIdx.z)) * GN + rA) * 72;
    float* pB = pA + 8 * 72;
#pragma unroll
    for (int nt = 0; nt < 8; ++nt) {
        int col = nt * 8 + c * 2;
        *(float2*)(pA + col) = make_float2(acc[nt][0], acc[nt][1]);
        *(float2*)(pB + col) = make_float2(acc[nt][2], acc[nt][3]);
    }
    if (c == 0) { pA[64] = acc[8][0]; pB[64] = acc[8][2]; }
}

// ---------------- layer-1 reduce: sum JS1 partials, ELU, bf16 store --------
__global__ void reduce_hbuf_kernel(const float* __restrict__ part,
                                   __nv_bfloat16* __restrict__ outB) {
    int id  = blockIdx.x * 256 + threadIdx.x;   // over GN*256 (2 cols each)
    int row = id >> 8;
    int cp  = (id & 255) * 2;                    // 0..510
    int h   = cp >> 6;
    int cl  = cp & 63;
    const float* r0 = part + (((size_t)(h * JS1 + 0)) * GN + row) * 72;
    const float* r1 = part + (((size_t)(h * JS1 + 1)) * GN + row) * 72;
    float2 n0 = *(const float2*)(r0 + cl);
    float2 n1 = *(const float2*)(r1 + cl);
    float inv = 1.f / (r0[64] + r1[64]);
    float v0 = (n0.x + n1.x) * inv;
    float v1 = (n0.y + n1.y) * inv;
    v0 = v0 > 0.f ? v0 : (ex2f(v0 * LOG2E) - 1.f);
    v1 = v1 > 0.f ? v1 : (ex2f(v1 * LOG2E) - 1.f);
    *(__nv_bfloat162*)(outB + (size_t)row * FCAT + cp) = __floats2bfloat162_rn(v0, v1);
}

// ---------------- layer-2 reduce: sum JS2 partials + ELU + log_softmax ----
__global__ void reduce_lsm_kernel(const float* __restrict__ part,
                                  float* __restrict__ out) {
    int row = blockIdx.x * 8 + (threadIdx.x >> 5);
    int ln  = threadIdx.x & 31;
    float n0 = 0.f, n1 = 0.f, d = 0.f;
#pragma unroll
    for (int js = 0; js < JS2; ++js) {
        const float* b = part + ((size_t)js * GN + row) * 72;
        n0 += b[ln]; n1 += b[ln + 32]; d += b[64];
    }
    float inv = 1.f / d;
    float v0 = n0 * inv, v1 = n1 * inv;
    v0 = v0 > 0.f ? v0 : (__expf(v0) - 1.f);
    v1 = v1 > 0.f ? v1 : (__expf(v1) - 1.f);
    float mx = fmaxf(v0, v1);
#pragma unroll
    for (int o = 16; o; o >>= 1) mx = fmaxf(mx, __shfl_xor_sync(0xffffffffu, mx, o));
    float s = __expf(v0 - mx) + __expf(v1 - mx);
#pragma unroll
    for (int o = 16; o; o >>= 1) s += __shfl_xor_sync(0xffffffffu, s, o);
    float l = mx + __logf(s);
    out[(size_t)row * 64 + ln]      = v0 - l;
    out[(size_t)row * 64 + ln + 32] = v1 - l;
}

// ---------------- launch ----------------
extern "C" void kernel_launch(void* const* d_in, const int* in_sizes, int n_in,
                              void* d_out, int out_size) {
    const float* x   = (const float*)d_in[0];
    const int*   adj = (const int*)d_in[1];
    const float* W   = (const float*)d_in[2];
    const float* a1  = (const float*)d_in[3];
    const float* a2  = (const float*)d_in[4];
    const float* W2  = (const float*)d_in[5];
    const float* a21 = (const float*)d_in[6];
    const float* a22 = (const float*)d_in[7];
    float* out = (float*)d_out;

    uint32_t* adjbits; unsigned* gmaxi;
    float *wh1, *s1, *s2, *e2, *e2b, *wh2, *s21, *s22, *e22, *e22b, *part;
    __nv_bfloat16 *xb, *Wb, *W2b, *whTb, *hbufb, *whT2b;
    cudaGetSymbolAddress((void**)&adjbits, g_adjbits);
    cudaGetSymbolAddress((void**)&gmaxi, g_gmaxi);
    cudaGetSymbolAddress((void**)&xb,    g_xb);
    cudaGetSymbolAddress((void**)&Wb,    g_Wb);
    cudaGetSymbolAddress((void**)&W2b,   g_W2b);
    cudaGetSymbolAddress((void**)&wh1,   g_wh1);
    cudaGetSymbolAddress((void**)&whTb,  g_whTb);
    cudaGetSymbolAddress((void**)&s1,    g_s1);
    cudaGetSymbolAddress((void**)&s2,    g_s2);
    cudaGetSymbolAddress((void**)&e2,    g_e2);
    cudaGetSymbolAddress((void**)&e2b,   g_e2b);
    cudaGetSymbolAddress((void**)&hbufb, g_hbufb);
    cudaGetSymbolAddress((void**)&wh2,   g_wh2);
    cudaGetSymbolAddress((void**)&whT2b, g_whT2b);
    cudaGetSymbolAddress((void**)&s21,   g_s21);
    cudaGetSymbolAddress((void**)&s22,   g_s22);
    cudaGetSymbolAddress((void**)&e22,   g_e22);
    cudaGetSymbolAddress((void**)&e22b,  g_e22b);
    cudaGetSymbolAddress((void**)&part,  g_part);

    pack_adj_kernel<<<(GN * GN) / 1024, 256>>>(adj, adjbits, gmaxi);
    cvt_all_kernel<<<(GN * FCAT + FCAT * FCAT + HIDF * FCAT) / 512, 256>>>(
        x, xb, W, Wb, W2, W2b);
    gemm_bf16_nt<<<dim3(FCAT / 64, GN / 128), 256>>>(xb, Wb, wh1, FCAT, FCAT);
    scores_kernel<<<(GN * GH) / 8, 256>>>(wh1, FCAT, GH, a1, a2, s1, s2, e2, e2b, gmaxi);
    transpose_cvt_kernel<<<dim3(FCAT / 32, GN / 32), dim3(32, 8)>>>(wh1, whTb, FCAT);
    attn_mma_kernel<JS1><<<dim3(GN / 128, GH, JS1), 256>>>(whTb, s1, s2, e2, e2b,
                                                           gmaxi, adjbits, part);
    reduce_hbuf_kernel<<<GN, 256>>>(part, hbufb);
    gemm_bf16_nt<<<dim3(1, GN / 128), 256>>>(hbufb, W2b, wh2, FCAT, HIDF);
    scores_kernel<<<GN / 8, 256>>>(wh2, HIDF, 1, a21, a22, s21, s22, e22, e22b,
                                   gmaxi + 8);
    transpose_cvt_kernel<<<dim3(HIDF / 32, GN / 32), dim3(32, 8)>>>(wh2, whT2b, HIDF);
    attn_mma_kernel<JS2><<<dim3(GN / 128, 1, JS2), 256>>>(whT2b, s21, s22, e22, e22b,
                                                          gmaxi + 8, adjbits, part);
    reduce_lsm_kernel<<<GN / 8, 256>>>(part, out);
}

// round 9
// speedup vs baseline: 11.5232x; 1.0813x over previous
#include <cuda_runtime.h>
#include <cuda_bf16.h>
#include <stdint.h>

#define GN 4096
#define GH 8
#define FCAT 512
#define HIDF 64
#define ADJW (GN/32)
#define JS1 2
#define JS2 16
#define LOG2E 1.4426950408889634f

// ---------------- scratch ----------------
__device__ uint32_t      g_adjbits[GN * ADJW];
__device__ __nv_bfloat16 g_xb[GN * FCAT];
__device__ __nv_bfloat16 g_Wb[FCAT * FCAT];
__device__ __nv_bfloat16 g_W2b[HIDF * FCAT];
__device__ float         g_wh1[GN * FCAT];
__device__ __nv_bfloat16 g_whTb[FCAT * GN];
__device__ float         g_s1[GH * GN];
__device__ float         g_s2[GH * GN];
__device__ float         g_e2[GH * GN];     // ex2(s2)
__device__ float         g_e2b[GH * GN];    // ex2(0.2*s2)
__device__ unsigned      g_gmaxi[16];
__device__ __nv_bfloat16 g_hbufb[GN * FCAT];
__device__ float         g_wh2[GN * HIDF];
__device__ __nv_bfloat16 g_whT2b[HIDF * GN];
__device__ float         g_s21[GN];
__device__ float         g_s22[GN];
__device__ float         g_e22[GN];
__device__ float         g_e22b[GN];
__device__ float         g_part[16 * GN * 72];    // 16 slots x [row][72]

__device__ __forceinline__ unsigned fenc(float f) {
    unsigned b = __float_as_uint(f);
    return (b & 0x80000000u) ? ~b : (b | 0x80000000u);
}
__device__ __forceinline__ float fdec(unsigned k) {
    return __uint_as_float((k & 0x80000000u) ? (k & 0x7fffffffu) : ~k);
}
__device__ __forceinline__ float ex2f(float x) {
    float y; asm("ex2.approx.f32 %0, %1;" : "=f"(y) : "f"(x)); return y;
}
__device__ __forceinline__ uint32_t sptr(const void* p) {
    return (uint32_t)__cvta_generic_to_shared(p);
}
__device__ __forceinline__ void ldsm4(uint32_t* r, uint32_t a) {
    asm volatile("ldmatrix.sync.aligned.m8n8.x4.shared.b16 {%0,%1,%2,%3}, [%4];"
                 : "=r"(r[0]), "=r"(r[1]), "=r"(r[2]), "=r"(r[3]) : "r"(a));
}
__device__ __forceinline__ void ldsm2(uint32_t* r, uint32_t a) {
    asm volatile("ldmatrix.sync.aligned.m8n8.x2.shared.b16 {%0,%1}, [%2];"
                 : "=r"(r[0]), "=r"(r[1]) : "r"(a));
}
__device__ __forceinline__ void cpa16(uint32_t dst, const void* src) {
    asm volatile("cp.async.cg.shared.global [%0], [%1], 16;" :: "r"(dst), "l"(src));
}
__device__ __forceinline__ void cpa_commit() {
    asm volatile("cp.async.commit_group;");
}
template<int N>
__device__ __forceinline__ void cpa_wait() {
    asm volatile("cp.async.wait_group %0;" :: "n"(N));
}
__device__ __forceinline__ void mma16816(float* d, const uint32_t* a,
                                         uint32_t b0, uint32_t b1) {
    asm volatile(
        "mma.sync.aligned.m16n8k16.row.col.f32.bf16.bf16.f32 "
        "{%0,%1,%2,%3}, {%4,%5,%6,%7}, {%8,%9}, {%0,%1,%2,%3};"
        : "+f"(d[0]), "+f"(d[1]), "+f"(d[2]), "+f"(d[3])
        : "r"(a[0]), "r"(a[1]), "r"(a[2]), "r"(a[3]), "r"(b0), "r"(b1));
}

// ---------------- pack adjacency (4x unrolled) + init gmax ----------------
__global__ void pack_adj_kernel(const int* __restrict__ adj,
                                uint32_t* __restrict__ bits,
                                unsigned* __restrict__ gmaxi) {
    if (blockIdx.x == 0 && threadIdx.x < 16) gmaxi[threadIdx.x] = 0u;
    int wg   = (blockIdx.x * 256 + threadIdx.x) >> 5;
    int lane = threadIdx.x & 31;
    int base = wg * 128;
    int v0 = adj[base + lane];
    int v1 = adj[base + 32 + lane];
    int v2 = adj[base + 64 + lane];
    int v3 = adj[base + 96 + lane];
    uint32_t b[4];
    b[0] = __ballot_sync(0xffffffffu, v0 > 0);
    b[1] = __ballot_sync(0xffffffffu, v1 > 0);
    b[2] = __ballot_sync(0xffffffffu, v2 > 0);
    b[3] = __ballot_sync(0xffffffffu, v3 > 0);
    if (lane < 4) bits[wg * 4 + lane] = b[lane];
}

// ---------------- fp32 -> bf16, all three inputs in one launch ------------
__global__ void cvt_all_kernel(const float* __restrict__ x, __nv_bfloat16* __restrict__ xb,
                               const float* __restrict__ W, __nv_bfloat16* __restrict__ Wb,
                               const float* __restrict__ W2, __nv_bfloat16* __restrict__ W2b) {
    const int NX = GN * FCAT / 2, NW = FCAT * FCAT / 2;
    int id = blockIdx.x * 256 + threadIdx.x;
    const float* src; __nv_bfloat16* dst; int off;
    if (id < NX)           { src = x;  dst = xb;  off = id; }
    else if (id < NX + NW) { src = W;  dst = Wb;  off = id - NX; }
    else                   { src = W2; dst = W2b; off = id - NX - NW; }
    float2 v = *(const float2*)(src + (size_t)off * 2);
    *(__nv_bfloat162*)(dst + (size_t)off * 2) = __floats2bfloat162_rn(v.x, v.y);
}

// ---------------- fp32 [GN][C] -> bf16 transposed [C][GN] ----------------
__global__ void transpose_cvt_kernel(const float* __restrict__ in,
                                     __nv_bfloat16* __restrict__ out, int C) {
    __shared__ float tile[32][33];
    int tx = threadIdx.x, ty = threadIdx.y;
    int c0 = blockIdx.x * 32;
    int r0 = blockIdx.y * 32;
#pragma unroll
    for (int k = 0; k < 4; ++k)
        tile[ty + k * 8][tx] = in[(size_t)(r0 + ty + k * 8) * C + c0 + tx];
    __syncthreads();
#pragma unroll
    for (int k = 0; k < 4; ++k)
        out[(size_t)(c0 + ty + k * 8) * GN + r0 + tx] =
            __float2bfloat16(tile[tx][ty + k * 8]);
}

// ---------------- bf16 NT GEMM, cp.async double-buffered (Kc=32) ----------
__global__ void __launch_bounds__(256, 3)
gemm_bf16_nt(const __nv_bfloat16* __restrict__ A,
             const __nv_bfloat16* __restrict__ B,
             float* __restrict__ C, int K, int Ncols) {
    __shared__ __nv_bfloat16 As[2][128 * 40];
    __shared__ __nv_bfloat16 Bs[2][64 * 40];

    const int t  = threadIdx.x;
    const int m0 = blockIdx.y * 128;
    const int n0 = blockIdx.x * 64;
    const int w = t >> 5, ln = t & 31;
    const int r = ln >> 2, c = ln & 3;

    const uint32_t aB = sptr(As[0]) + (uint32_t)(((w * 16 + (ln & 15)) * 40 +
                                                  ((ln >> 4) & 1) * 8) * 2);
    const uint32_t bB = sptr(Bs[0]) + (uint32_t)((((ln & 7) + ((ln >> 4) & 1) * 8) * 40 +
                                                  ((ln >> 3) & 1) * 8) * 2);
    const uint32_t ABUF = 128 * 40 * 2;
    const uint32_t BBUF = 64 * 40 * 2;

    float acc[8][4];
#pragma unroll
    for (int nt = 0; nt < 8; ++nt)
#pragma unroll
        for (int q = 0; q < 4; ++q) acc[nt][q] = 0.f;

    auto g_issue = [&](int ki) {
        int buf = ki & 1;
        int kc = ki * 32;
#pragma unroll
        for (int it = 0; it < 2; ++it) {
            int idx = it * 256 + t;
            int row = idx >> 2, u = idx & 3;
            cpa16(sptr(&As[buf][row * 40 + u * 8]),
                  A + (size_t)(m0 + row) * K + kc + u * 8);
        }
        {
            int row = t >> 2, u = t & 3;
            cpa16(sptr(&Bs[buf][row * 40 + u * 8]),
                  B + (size_t)(n0 + row) * K + kc + u * 8);
        }
    };

    const int NK = K / 32;
    g_issue(0); cpa_commit();
    for (int ki = 0; ki < NK; ++ki) {
        if (ki + 1 < NK) { g_issue(ki + 1); cpa_commit(); cpa_wait<1>(); }
        else             { cpa_wait<0>(); }
        __syncthreads();
        const int buf = ki & 1;
#pragma unroll
        for (int kt = 0; kt < 2; ++kt) {
            uint32_t a[4];
            ldsm4(a, aB + buf * ABUF + kt * 32);
#pragma unroll
            for (int p = 0; p < 4; ++p) {
                uint32_t b[4];
                ldsm4(b, bB + buf * BBUF + p * 1280 + kt * 32);
                mma16816(acc[2 * p],     a, b[0], b[1]);
                mma16816(acc[2 * p + 1], a, b[2], b[3]);
            }
        }
        __syncthreads();
    }
    int rA = m0 + w * 16 + r;
#pragma unroll
    for (int nt = 0; nt < 8; ++nt) {
        int col = n0 + nt * 8 + c * 2;
        *(float2*)&C[(size_t)rA * Ncols + col]       = make_float2(acc[nt][0], acc[nt][1]);
        *(float2*)&C[(size_t)(rA + 8) * Ncols + col] = make_float2(acc[nt][2], acc[nt][3]);
    }
}

// ---------------- layer-1 scores: warp per row, all 8 heads ---------------
__global__ void scores1_kernel(const float* __restrict__ wh1,
                               const float* __restrict__ a1, const float* __restrict__ a2,
                               float* __restrict__ s1, float* __restrict__ s2,
                               float* __restrict__ e2, float* __restrict__ e2b,
                               unsigned* __restrict__ gmaxi) {
    __shared__ float a1s[FCAT], a2s[FCAT];
    int t = threadIdx.x;
    for (int idx = t; idx < FCAT; idx += 256) { a1s[idx] = a1[idx]; a2s[idx] = a2[idx]; }
    __syncthreads();
    int w = t >> 5, ln = t & 31;
    int i = blockIdx.x * 8 + w;
    const float4* row = (const float4*)(wh1 + (size_t)i * FCAT);
    float p1 = 0.f, p2 = 0.f;
#pragma unroll
    for (int q = 0; q < 4; ++q) {
        float4 v  = row[ln * 4 + q];                      // lane covers [16ln,16ln+16)
        float4 x1 = *(const float4*)&a1s[ln * 16 + q * 4];
        float4 x2 = *(const float4*)&a2s[ln * 16 + q * 4];
        p1 += v.x * x1.x + v.y * x1.y + v.z * x1.z + v.w * x1.w;
        p2 += v.x * x2.x + v.y * x2.y + v.z * x2.z + v.w * x2.w;
    }
    p1 += __shfl_down_sync(0xffffffffu, p1, 2);
    p2 += __shfl_down_sync(0xffffffffu, p2, 2);
    p1 += __shfl_down_sync(0xffffffffu, p1, 1);
    p2 += __shfl_down_sync(0xffffffffu, p2, 1);
    if ((ln & 3) == 0) {
        int h = ln >> 2;                                  // head = 16ln/64
        p1 *= LOG2E; p2 *= LOG2E;
        s1[h * GN + i]  = p1;
        s2[h * GN + i]  = p2;
        e2[h * GN + i]  = ex2f(p2);
        e2b[h * GN + i] = ex2f(0.2f * p2);
        atomicMax(&gmaxi[h], fenc(p2));
    }
}

// ---------------- layer-2 scores (warp per (i,h)) --------------------------
__global__ void scores_kernel(const float* __restrict__ wh, int stride, int nH,
                              const float* __restrict__ a1, const float* __restrict__ a2,
                              float* __restrict__ s1, float* __restrict__ s2,
                              float* __restrict__ e2, float* __restrict__ e2b,
                              unsigned* __restrict__ gmaxi) {
    int w    = blockIdx.x * 8 + (threadIdx.x >> 5);
    int lane = threadIdx.x & 31;
    int i = w / nH, h = w % nH;
    const float* base = wh + (size_t)i * stride + h * 64;
    float v0 = base[lane], v1 = base[lane + 32];
    float p1 = v0 * a1[h * 64 + lane] + v1 * a1[h * 64 + lane + 32];
    float p2 = v0 * a2[h * 64 + lane] + v1 * a2[h * 64 + lane + 32];
#pragma unroll
    for (int o = 16; o; o >>= 1) {
        p1 += __shfl_down_sync(0xffffffffu, p1, o);
        p2 += __shfl_down_sync(0xffffffffu, p2, o);
    }
    if (lane == 0) {
        p1 *= LOG2E; p2 *= LOG2E;
        s1[h * GN + i]  = p1;
        s2[h * GN + i]  = p2;
        e2[h * GN + i]  = ex2f(p2);
        e2b[h * GN + i] = ex2f(0.2f * p2);
        atomicMax(&gmaxi[h], fenc(p2));
    }
}

// ---------------- fused masked softmax + att@wh, 1 barrier per tile -------
// Block: 256 thr; warp w owns m-tile w. ps produce/consume is WARP-LOCAL
// (thread t writes ps row t>>1; warp w ldsm-reads rows 16w..16w+15), so
// phase1->phase2 needs only __syncwarp. s2/E2/E2b staged per-tile via the
// same cp.async group as the wh tile (double buffered). Per tile:
// wait<0>, syncthreads, issue(tt+1), phase1, syncwarp, phase2. The single
// syncthreads resolves cp.async visibility + ps/whs WAR vs phase2(tt-1).
// Static smem: 18K (ps) + 20.25K (whs) + 1.5K (tables) = 40.7K < 48K cap.
template<int JS>
__global__ void __launch_bounds__(256, 3)
attn_mma_kernel(const __nv_bfloat16* __restrict__ whT,
                const float* __restrict__ s1g, const float* __restrict__ s2g,
                const float* __restrict__ e2g, const float* __restrict__ e2bg,
                const unsigned* __restrict__ gmaxi,
                const uint32_t* __restrict__ adjbits,
                float* __restrict__ part) {
    constexpr int NT = (GN / JS) / 64;
    __shared__ __nv_bfloat16 ps[128 * 72];
    __shared__ __nv_bfloat16 whs[2][72 * 72];
    __shared__ float s2t[2][64];
    __shared__ float e2t[2][64];
    __shared__ float e2bt[2][64];

    const int t  = threadIdx.x;
    const int i0 = blockIdx.x * 128;
    const int h  = blockIdx.y;
    const int jbase = blockIdx.z * (GN / JS);

    const __nv_bfloat16* whTh = whT + (size_t)h * 64 * GN;
    const float* s2h  = s2g  + h * GN;
    const float* e2h  = e2g  + h * GN;
    const float* e2bh = e2bg + h * GN;
    uint32_t* psW = reinterpret_cast<uint32_t*>(ps);

    // constant rows 64..71 of both whs buffers (row 64 = ones -> den column)
#pragma unroll
    for (int b = 0; b < 2; ++b)
        for (int idx = t; idx < 8 * 36; idx += 256) {
            int rr = idx / 36, wd = idx - rr * 36;
            reinterpret_cast<uint32_t*>(whs[b])[(64 + rr) * 36 + wd] =
                (rr == 0) ? 0x3F803F80u : 0u;
        }

    auto issue_tile = [&](int tt) {
        int buf = tt & 1;
        int j0 = jbase + tt * 64;
#pragma unroll
        for (int it = 0; it < 2; ++it) {
            int idx = it * 256 + t;
            int f = idx >> 3, u = idx & 7;
            cpa16(sptr(&whs[buf][f * 72 + u * 8]), whTh + (size_t)f * GN + j0 + u * 8);
        }
        if (t < 16)      cpa16(sptr(&s2t[buf][t * 4]),         s2h  + j0 + t * 4);
        else if (t < 32) cpa16(sptr(&e2t[buf][(t - 16) * 4]),  e2h  + j0 + (t - 16) * 4);
        else if (t < 48) cpa16(sptr(&e2bt[buf][(t - 32) * 4]), e2bh + j0 + (t - 32) * 4);
    };

    issue_tile(0);
    cpa_commit();

    const int rt = t >> 1, jh = t & 1;          // phase-1: row / adj-word half
    const float s1i = s1g[h * GN + i0 + rt];
    const float gme = s1i + fdec(gmaxi[h]);
    const float m   = fmaxf(gme, 0.2f * gme);
    const float ci  = ex2f(s1i - m);
    const float ci2 = ex2f(0.2f * s1i - m);
    const float ns1 = -s1i;

    const int w = t >> 5, ln = t & 31;
    const int r = ln >> 2, c = ln & 3;

    const uint32_t psB = sptr(ps) + (uint32_t)(((w * 16 + (ln & 15)) * 72 +
                                                ((ln >> 4) & 1) * 8) * 2);
    const uint32_t whB0 = sptr(whs[0]) + (uint32_t)((((ln & 7) + ((ln >> 4) & 1) * 8) * 72 +
                                                     ((ln >> 3) & 1) * 8) * 2);
    const uint32_t dnB0 = sptr(whs[0]) + (uint32_t)(((64 + (ln & 7)) * 72 +
                                                     ((ln >> 3) & 1) * 8) * 2);
    const uint32_t bufStride = (uint32_t)(72 * 72 * 2);

    float acc[9][4];
#pragma unroll
    for (int nt = 0; nt < 9; ++nt)
#pragma unroll
        for (int q = 0; q < 4; ++q) acc[nt][q] = 0.f;

    const uint32_t* adjRow = adjbits + (size_t)(i0 + rt) * ADJW;

    for (int tt = 0; tt < NT; ++tt) {
        cpa_wait<0>();           // tile-tt copies done (all groups drained)
        __syncthreads();         // block-wide: data visible; phase2(tt-1) done
        if (tt + 1 < NT) { issue_tile(tt + 1); cpa_commit(); }

        const int buf = tt & 1;
        const int j0  = jbase + tt * 64;

        // ---- phase 1: 32 p's (row rt, adj word jh), tables in smem ----
        const uint32_t wv = adjRow[(j0 >> 5) + jh];
        const float2* s2p  = reinterpret_cast<const float2*>(s2t[buf]  + jh * 32);
        const float2* e2p  = reinterpret_cast<const float2*>(e2t[buf]  + jh * 32);
        const float2* e2bp = reinterpret_cast<const float2*>(e2bt[buf] + jh * 32);
#pragma unroll
        for (int u = 0; u < 4; ++u) {
            uint32_t pk[4];
#pragma unroll
            for (int q = 0; q < 4; ++q) {
                int j = u * 8 + q * 2;
                float2 sv = s2p[u * 4 + q];
                float2 ev = e2p[u * 4 + q];
                float2 bv = e2bp[u * 4 + q];
                float p0 = (sv.x > ns1) ? ev.x * ci : bv.x * ci2;
                float p1 = (sv.y > ns1) ? ev.y * ci : bv.y * ci2;
                p0 = ((wv >> j) & 1u)       ? p0 : 0.f;
                p1 = ((wv >> (j + 1)) & 1u) ? p1 : 0.f;
                __nv_bfloat162 h2 = __floats2bfloat162_rn(p0, p1);
                pk[q] = *reinterpret_cast<uint32_t*>(&h2);
            }
            *(uint4*)(psW + rt * 36 + jh * 16 + u * 4) =
                make_uint4(pk[0], pk[1], pk[2], pk[3]);
        }
        __syncwarp();            // ps is warp-local: warp-level fence suffices

        // ---- phase 2: warp w -> m-tile w, all 9 n-tiles ----
        const uint32_t whB = whB0 + buf * bufStride;
        const uint32_t dnB = dnB0 + buf * bufStride;
#pragma unroll
        for (int kt = 0; kt < 4; ++kt) {
            uint32_t a[4];
            ldsm4(a, psB + kt * 32);
#pragma unroll
            for (int p = 0; p < 4; ++p) {
                uint32_t b[4];
                ldsm4(b, whB + p * 2304 + kt * 32);
                mma16816(acc[2 * p],     a, b[0], b[1]);
                mma16816(acc[2 * p + 1], a, b[2], b[3]);
            }
            uint32_t d[2];
            ldsm2(d, dnB + kt * 32);
            mma16816(acc[8], a, d[0], d[1]);
        }
        // no trailing barrier: next-iter syncthreads covers WAR hazards
    }

    // ---- store partials: slot = h*JS + z ----
    int rA = i0 + w * 16 + r;
    float* pA = part + (((size_t)(h * JS + blockIdx.z)) * GN + rA) * 72;
    float* pB = pA + 8 * 72;
#pragma unroll
    for (int nt = 0; nt < 8; ++nt) {
        int col = nt * 8 + c * 2;
        *(float2*)(pA + col) = make_float2(acc[nt][0], acc[nt][1]);
        *(float2*)(pB + col) = make_float2(acc[nt][2], acc[nt][3]);
    }
    if (c == 0) { pA[64] = acc[8][0]; pB[64] = acc[8][2]; }
}

// ---------------- layer-1 reduce: sum JS1 partials, ELU, bf16 store --------
__global__ void reduce_hbuf_kernel(const float* __restrict__ part,
                                   __nv_bfloat16* __restrict__ outB) {
    int id  = blockIdx.x * 256 + threadIdx.x;
    int row = id >> 8;
    int cp  = (id & 255) * 2;
    int h   = cp >> 6;
    int cl  = cp & 63;
    const float* r0 = part + (((size_t)(h * JS1 + 0)) * GN + row) * 72;
    const float* r1 = part + (((size_t)(h * JS1 + 1)) * GN + row) * 72;
    float2 n0 = *(const float2*)(r0 + cl);
    float2 n1 = *(const float2*)(r1 + cl);
    float inv = 1.f / (r0[64] + r1[64]);
    float v0 = (n0.x + n1.x) * inv;
    float v1 = (n0.y + n1.y) * inv;
    v0 = v0 > 0.f ? v0 : (ex2f(v0 * LOG2E) - 1.f);
    v1 = v1 > 0.f ? v1 : (ex2f(v1 * LOG2E) - 1.f);
    *(__nv_bfloat162*)(outB + (size_t)row * FCAT + cp) = __floats2bfloat162_rn(v0, v1);
}

// ---------------- layer-2 reduce: sum JS2 partials + ELU + log_softmax ----
__global__ void reduce_lsm_kernel(const float* __restrict__ part,
                                  float* __restrict__ out) {
    int row = blockIdx.x * 8 + (threadIdx.x >> 5);
    int ln  = threadIdx.x & 31;
    float n0 = 0.f, n1 = 0.f, d = 0.f;
#pragma unroll
    for (int js = 0; js < JS2; ++js) {
        const float* b = part + ((size_t)js * GN + row) * 72;
        n0 += b[ln]; n1 += b[ln + 32]; d += b[64];
    }
    float inv = 1.f / d;
    float v0 = n0 * inv, v1 = n1 * inv;
    v0 = v0 > 0.f ? v0 : (__expf(v0) - 1.f);
    v1 = v1 > 0.f ? v1 : (__expf(v1) - 1.f);
    float mx = fmaxf(v0, v1);
#pragma unroll
    for (int o = 16; o; o >>= 1) mx = fmaxf(mx, __shfl_xor_sync(0xffffffffu, mx, o));
    float s = __expf(v0 - mx) + __expf(v1 - mx);
#pragma unroll
    for (int o = 16; o; o >>= 1) s += __shfl_xor_sync(0xffffffffu, s, o);
    float l = mx + __logf(s);
    out[(size_t)row * 64 + ln]      = v0 - l;
    out[(size_t)row * 64 + ln + 32] = v1 - l;
}

// ---------------- launch ----------------
extern "C" void kernel_launch(void* const* d_in, const int* in_sizes, int n_in,
                              void* d_out, int out_size) {
    const float* x   = (const float*)d_in[0];
    const int*   adj = (const int*)d_in[1];
    const float* W   = (const float*)d_in[2];
    const float* a1  = (const float*)d_in[3];
    const float* a2  = (const float*)d_in[4];
    const float* W2  = (const float*)d_in[5];
    const float* a21 = (const float*)d_in[6];
    const float* a22 = (const float*)d_in[7];
    float* out = (float*)d_out;

    uint32_t* adjbits; unsigned* gmaxi;
    float *wh1, *s1, *s2, *e2, *e2b, *wh2, *s21, *s22, *e22, *e22b, *part;
    __nv_bfloat16 *xb, *Wb, *W2b, *whTb, *hbufb, *whT2b;
    cudaGetSymbolAddress((void**)&adjbits, g_adjbits);
    cudaGetSymbolAddress((void**)&gmaxi, g_gmaxi);
    cudaGetSymbolAddress((void**)&xb,    g_xb);
    cudaGetSymbolAddress((void**)&Wb,    g_Wb);
    cudaGetSymbolAddress((void**)&W2b,   g_W2b);
    cudaGetSymbolAddress((void**)&wh1,   g_wh1);
    cudaGetSymbolAddress((void**)&whTb,  g_whTb);
    cudaGetSymbolAddress((void**)&s1,    g_s1);
    cudaGetSymbolAddress((void**)&s2,    g_s2);
    cudaGetSymbolAddress((void**)&e2,    g_e2);
    cudaGetSymbolAddress((void**)&e2b,   g_e2b);
    cudaGetSymbolAddress((void**)&hbufb, g_hbufb);
    cudaGetSymbolAddress((void**)&wh2,   g_wh2);
    cudaGetSymbolAddress((void**)&whT2b, g_whT2b);
    cudaGetSymbolAddress((void**)&s21,   g_s21);
    cudaGetSymbolAddress((void**)&s22,   g_s22);
    cudaGetSymbolAddress((void**)&e22,   g_e22);
    cudaGetSymbolAddress((void**)&e22b,  g_e22b);
    cudaGetSymbolAddress((void**)&part,  g_part);

    pack_adj_kernel<<<(GN * GN) / 1024, 256>>>(adj, adjbits, gmaxi);
    cvt_all_kernel<<<(GN * FCAT + FCAT * FCAT + HIDF * FCAT) / 512, 256>>>(
        x, xb, W, Wb, W2, W2b);
    gemm_bf16_nt<<<dim3(FCAT / 64, GN / 128), 256>>>(xb, Wb, wh1, FCAT, FCAT);
    scores1_kernel<<<GN / 8, 256>>>(wh1, a1, a2, s1, s2, e2, e2b, gmaxi);
    transpose_cvt_kernel<<<dim3(FCAT / 32, GN / 32), dim3(32, 8)>>>(wh1, whTb, FCAT);
    attn_mma_kernel<JS1><<<dim3(GN / 128, GH, JS1), 256>>>(whTb, s1, s2, e2, e2b,
                                                           gmaxi, adjbits, part);
    reduce_hbuf_kernel<<<GN, 256>>>(part, hbufb);
    gemm_bf16_nt<<<dim3(1, GN / 128), 256>>>(hbufb, W2b, wh2, FCAT, HIDF);
    scores_kernel<<<GN / 8, 256>>>(wh2, HIDF, 1, a21, a22, s21, s22, e22, e22b,
                                   gmaxi + 8);
    transpose_cvt_kernel<<<dim3(HIDF / 32, GN / 32), dim3(32, 8)>>>(wh2, whT2b, HIDF);
    attn_mma_kernel<JS2><<<dim3(GN / 128, 1, JS2), 256>>>(whT2b, s21, s22, e22, e22b,
                                                          gmaxi + 8, adjbits, part);
    reduce_lsm_kernel<<<GN / 8, 256>>>(part, out);
}

// round 11
// speedup vs baseline: 13.3390x; 1.1576x over previous
#include <cuda_runtime.h>
#include <cuda_bf16.h>
#include <stdint.h>

#define GN 4096
#define GH 8
#define FCAT 512
#define HIDF 64
#define ADJW (GN/32)
#define JS1 4
#define JS2 16
#define LOG2E 1.4426950408889634f

// ---------------- scratch ----------------
__device__ uint32_t      g_adjbits[GN * ADJW];
__device__ __nv_bfloat16 g_xb[GN * FCAT];
__device__ __nv_bfloat16 g_Wb[FCAT * FCAT];
__device__ __nv_bfloat16 g_W2b[HIDF * FCAT];
__device__ float         g_wh1[GN * FCAT];
__device__ __nv_bfloat16 g_whTb[FCAT * GN];
__device__ float         g_s1[GH * GN];
__device__ float         g_s2[GH * GN];
__device__ float         g_e2[GH * GN];     // ex2(s2)
__device__ float         g_e2b[GH * GN];    // ex2(0.2*s2)
__device__ unsigned      g_gmaxi[16];
__device__ __nv_bfloat16 g_hbufb[GN * FCAT];
__device__ float         g_wh2[GN * HIDF];
__device__ __nv_bfloat16 g_whT2b[HIDF * GN];
__device__ float         g_s21[GN];
__device__ float         g_s22[GN];
__device__ float         g_e22[GN];
__device__ float         g_e22b[GN];
__device__ float         g_part[32 * GN * 72];    // 32 slots x [row][72]

__device__ __forceinline__ unsigned fenc(float f) {
    unsigned b = __float_as_uint(f);
    return (b & 0x80000000u) ? ~b : (b | 0x80000000u);
}
__device__ __forceinline__ float fdec(unsigned k) {
    return __uint_as_float((k & 0x80000000u) ? (k & 0x7fffffffu) : ~k);
}
__device__ __forceinline__ float ex2f(float x) {
    float y; asm("ex2.approx.f32 %0, %1;" : "=f"(y) : "f"(x)); return y;
}
__device__ __forceinline__ uint32_t sptr(const void* p) {
    return (uint32_t)__cvta_generic_to_shared(p);
}
__device__ __forceinline__ void ldsm4(uint32_t* r, uint32_t a) {
    asm volatile("ldmatrix.sync.aligned.m8n8.x4.shared.b16 {%0,%1,%2,%3}, [%4];"
                 : "=r"(r[0]), "=r"(r[1]), "=r"(r[2]), "=r"(r[3]) : "r"(a));
}
__device__ __forceinline__ void ldsm2(uint32_t* r, uint32_t a) {
    asm volatile("ldmatrix.sync.aligned.m8n8.x2.shared.b16 {%0,%1}, [%2];"
                 : "=r"(r[0]), "=r"(r[1]) : "r"(a));
}
__device__ __forceinline__ void cpa16(uint32_t dst, const void* src) {
    asm volatile("cp.async.cg.shared.global [%0], [%1], 16;" :: "r"(dst), "l"(src));
}
__device__ __forceinline__ void cpa_commit() {
    asm volatile("cp.async.commit_group;");
}
template<int N>
__device__ __forceinline__ void cpa_wait() {
    asm volatile("cp.async.wait_group %0;" :: "n"(N));
}
__device__ __forceinline__ void mma16816(float* d, const uint32_t* a,
                                         uint32_t b0, uint32_t b1) {
    asm volatile(
        "mma.sync.aligned.m16n8k16.row.col.f32.bf16.bf16.f32 "
        "{%0,%1,%2,%3}, {%4,%5,%6,%7}, {%8,%9}, {%0,%1,%2,%3};"
        : "+f"(d[0]), "+f"(d[1]), "+f"(d[2]), "+f"(d[3])
        : "r"(a[0]), "r"(a[1]), "r"(a[2]), "r"(a[3]), "r"(b0), "r"(b1));
}

// ---------------- pack adjacency (4x unrolled) + init gmax ----------------
__global__ void pack_adj_kernel(const int* __restrict__ adj,
                                uint32_t* __restrict__ bits,
                                unsigned* __restrict__ gmaxi) {
    if (blockIdx.x == 0 && threadIdx.x < 16) gmaxi[threadIdx.x] = 0u;
    int wg   = (blockIdx.x * 256 + threadIdx.x) >> 5;
    int lane = threadIdx.x & 31;
    int base = wg * 128;
    int v0 = adj[base + lane];
    int v1 = adj[base + 32 + lane];
    int v2 = adj[base + 64 + lane];
    int v3 = adj[base + 96 + lane];
    uint32_t b[4];
    b[0] = __ballot_sync(0xffffffffu, v0 > 0);
    b[1] = __ballot_sync(0xffffffffu, v1 > 0);
    b[2] = __ballot_sync(0xffffffffu, v2 > 0);
    b[3] = __ballot_sync(0xffffffffu, v3 > 0);
    if (lane < 4) bits[wg * 4 + lane] = b[lane];
}

// ---------------- fp32 -> bf16, all three inputs in one launch ------------
__global__ void cvt_all_kernel(const float* __restrict__ x, __nv_bfloat16* __restrict__ xb,
                               const float* __restrict__ W, __nv_bfloat16* __restrict__ Wb,
                               const float* __restrict__ W2, __nv_bfloat16* __restrict__ W2b) {
    const int NX = GN * FCAT / 2, NW = FCAT * FCAT / 2;
    int id = blockIdx.x * 256 + threadIdx.x;
    const float* src; __nv_bfloat16* dst; int off;
    if (id < NX)           { src = x;  dst = xb;  off = id; }
    else if (id < NX + NW) { src = W;  dst = Wb;  off = id - NX; }
    else                   { src = W2; dst = W2b; off = id - NX - NW; }
    float2 v = *(const float2*)(src + (size_t)off * 2);
    *(__nv_bfloat162*)(dst + (size_t)off * 2) = __floats2bfloat162_rn(v.x, v.y);
}

// ---------------- fp32 [GN][C] -> bf16 transposed [C][GN] ----------------
__global__ void transpose_cvt_kernel(const float* __restrict__ in,
                                     __nv_bfloat16* __restrict__ out, int C) {
    __shared__ float tile[32][33];
    int tx = threadIdx.x, ty = threadIdx.y;
    int c0 = blockIdx.x * 32;
    int r0 = blockIdx.y * 32;
#pragma unroll
    for (int k = 0; k < 4; ++k)
        tile[ty + k * 8][tx] = in[(size_t)(r0 + ty + k * 8) * C + c0 + tx];
    __syncthreads();
#pragma unroll
    for (int k = 0; k < 4; ++k)
        out[(size_t)(c0 + ty + k * 8) * GN + r0 + tx] =
            __float2bfloat16(tile[tx][ty + k * 8]);
}

// ---------------- bf16 NT GEMM, cp.async double-buffered (Kc=32) ----------
__global__ void __launch_bounds__(256, 3)
gemm_bf16_nt(const __nv_bfloat16* __restrict__ A,
             const __nv_bfloat16* __restrict__ B,
             float* __restrict__ C, int K, int Ncols) {
    __shared__ __nv_bfloat16 As[2][128 * 40];
    __shared__ __nv_bfloat16 Bs[2][64 * 40];

    const int t  = threadIdx.x;
    const int m0 = blockIdx.y * 128;
    const int n0 = blockIdx.x * 64;
    const int w = t >> 5, ln = t & 31;
    const int r = ln >> 2, c = ln & 3;

    const uint32_t aB = sptr(As[0]) + (uint32_t)(((w * 16 + (ln & 15)) * 40 +
                                                  ((ln >> 4) & 1) * 8) * 2);
    const uint32_t bB = sptr(Bs[0]) + (uint32_t)((((ln & 7) + ((ln >> 4) & 1) * 8) * 40 +
                                                  ((ln >> 3) & 1) * 8) * 2);
    const uint32_t ABUF = 128 * 40 * 2;
    const uint32_t BBUF = 64 * 40 * 2;

    float acc[8][4];
#pragma unroll
    for (int nt = 0; nt < 8; ++nt)
#pragma unroll
        for (int q = 0; q < 4; ++q) acc[nt][q] = 0.f;

    auto g_issue = [&](int ki) {
        int buf = ki & 1;
        int kc = ki * 32;
#pragma unroll
        for (int it = 0; it < 2; ++it) {
            int idx = it * 256 + t;
            int row = idx >> 2, u = idx & 3;
            cpa16(sptr(&As[buf][row * 40 + u * 8]),
                  A + (size_t)(m0 + row) * K + kc + u * 8);
        }
        {
            int row = t >> 2, u = t & 3;
            cpa16(sptr(&Bs[buf][row * 40 + u * 8]),
                  B + (size_t)(n0 + row) * K + kc + u * 8);
        }
    };

    const int NK = K / 32;
    g_issue(0); cpa_commit();
    for (int ki = 0; ki < NK; ++ki) {
        if (ki + 1 < NK) { g_issue(ki + 1); cpa_commit(); cpa_wait<1>(); }
        else             { cpa_wait<0>(); }
        __syncthreads();
        const int buf = ki & 1;
#pragma unroll
        for (int kt = 0; kt < 2; ++kt) {
            uint32_t a[4];
            ldsm4(a, aB + buf * ABUF + kt * 32);
#pragma unroll
            for (int p = 0; p < 4; ++p) {
                uint32_t b[4];
                ldsm4(b, bB + buf * BBUF + p * 1280 + kt * 32);
                mma16816(acc[2 * p],     a, b[0], b[1]);
                mma16816(acc[2 * p + 1], a, b[2], b[3]);
            }
        }
        __syncthreads();
    }
    int rA = m0 + w * 16 + r;
#pragma unroll
    for (int nt = 0; nt < 8; ++nt) {
        int col = n0 + nt * 8 + c * 2;
        *(float2*)&C[(size_t)rA * Ncols + col]       = make_float2(acc[nt][0], acc[nt][1]);
        *(float2*)&C[(size_t)(rA + 8) * Ncols + col] = make_float2(acc[nt][2], acc[nt][3]);
    }
}

// ---------------- layer-1 scores: warp per row, all 8 heads ---------------
__global__ void scores1_kernel(const float* __restrict__ wh1,
                               const float* __restrict__ a1, const float* __restrict__ a2,
                               float* __restrict__ s1, float* __restrict__ s2,
                               float* __restrict__ e2, float* __restrict__ e2b,
                               unsigned* __restrict__ gmaxi) {
    __shared__ float a1s[FCAT], a2s[FCAT];
    int t = threadIdx.x;
    for (int idx = t; idx < FCAT; idx += 256) { a1s[idx] = a1[idx]; a2s[idx] = a2[idx]; }
    __syncthreads();
    int w = t >> 5, ln = t & 31;
    int i = blockIdx.x * 8 + w;
    const float4* row = (const float4*)(wh1 + (size_t)i * FCAT);
    float p1 = 0.f, p2 = 0.f;
#pragma unroll
    for (int q = 0; q < 4; ++q) {
        float4 v  = row[ln * 4 + q];
        float4 x1 = *(const float4*)&a1s[ln * 16 + q * 4];
        float4 x2 = *(const float4*)&a2s[ln * 16 + q * 4];
        p1 += v.x * x1.x + v.y * x1.y + v.z * x1.z + v.w * x1.w;
        p2 += v.x * x2.x + v.y * x2.y + v.z * x2.z + v.w * x2.w;
    }
    p1 += __shfl_down_sync(0xffffffffu, p1, 2);
    p2 += __shfl_down_sync(0xffffffffu, p2, 2);
    p1 += __shfl_down_sync(0xffffffffu, p1, 1);
    p2 += __shfl_down_sync(0xffffffffu, p2, 1);
    if ((ln & 3) == 0) {
        int h = ln >> 2;
        p1 *= LOG2E; p2 *= LOG2E;
        s1[h * GN + i]  = p1;
        s2[h * GN + i]  = p2;
        e2[h * GN + i]  = ex2f(p2);
        e2b[h * GN + i] = ex2f(0.2f * p2);
        atomicMax(&gmaxi[h], fenc(p2));
    }
}

// ---------------- layer-2 scores (warp per (i,h)) --------------------------
__global__ void scores_kernel(const float* __restrict__ wh, int stride, int nH,
                              const float* __restrict__ a1, const float* __restrict__ a2,
                              float* __restrict__ s1, float* __restrict__ s2,
                              float* __restrict__ e2, float* __restrict__ e2b,
                              unsigned* __restrict__ gmaxi) {
    int w    = blockIdx.x * 8 + (threadIdx.x >> 5);
    int lane = threadIdx.x & 31;
    int i = w / nH, h = w % nH;
    const float* base = wh + (size_t)i * stride + h * 64;
    float v0 = base[lane], v1 = base[lane + 32];
    float p1 = v0 * a1[h * 64 + lane] + v1 * a1[h * 64 + lane + 32];
    float p2 = v0 * a2[h * 64 + lane] + v1 * a2[h * 64 + lane + 32];
#pragma unroll
    for (int o = 16; o; o >>= 1) {
        p1 += __shfl_down_sync(0xffffffffu, p1, o);
        p2 += __shfl_down_sync(0xffffffffu, p2, o);
    }
    if (lane == 0) {
        p1 *= LOG2E; p2 *= LOG2E;
        s1[h * GN + i]  = p1;
        s2[h * GN + i]  = p2;
        e2[h * GN + i]  = ex2f(p2);
        e2b[h * GN + i] = ex2f(0.2f * p2);
        atomicMax(&gmaxi[h], fenc(p2));
    }
}

// ---------------- fused masked softmax + att@wh, 1 barrier per tile -------
// Phase-1 uses p = max(E2[j]*ci, E2b[j]*ci2): exp2 monotone => max commutes,
// bitwise identical to the leaky select, no s2 table needed, no predicates.
template<int JS>
__global__ void __launch_bounds__(256, 3)
attn_mma_kernel(const __nv_bfloat16* __restrict__ whT,
                const float* __restrict__ s1g,
                const float* __restrict__ e2g, const float* __restrict__ e2bg,
                const unsigned* __restrict__ gmaxi,
                const uint32_t* __restrict__ adjbits,
                float* __restrict__ part) {
    constexpr int NT = (GN / JS) / 64;
    __shared__ __nv_bfloat16 ps[128 * 72];
    __shared__ __nv_bfloat16 whs[2][72 * 72];
    __shared__ float e2t[2][64];
    __shared__ float e2bt[2][64];

    const int t  = threadIdx.x;
    const int i0 = blockIdx.x * 128;
    const int h  = blockIdx.y;
    const int jbase = blockIdx.z * (GN / JS);

    const __nv_bfloat16* whTh = whT + (size_t)h * 64 * GN;
    const float* e2h  = e2g  + h * GN;
    const float* e2bh = e2bg + h * GN;
    uint32_t* psW = reinterpret_cast<uint32_t*>(ps);

    // constant rows 64..71 of both whs buffers (row 64 = ones -> den column)
#pragma unroll
    for (int b = 0; b < 2; ++b)
        for (int idx = t; idx < 8 * 36; idx += 256) {
            int rr = idx / 36, wd = idx - rr * 36;
            reinterpret_cast<uint32_t*>(whs[b])[(64 + rr) * 36 + wd] =
                (rr == 0) ? 0x3F803F80u : 0u;
        }

    auto issue_tile = [&](int tt) {
        int buf = tt & 1;
        int j0 = jbase + tt * 64;
#pragma unroll
        for (int it = 0; it < 2; ++it) {
            int idx = it * 256 + t;
            int f = idx >> 3, u = idx & 7;
            cpa16(sptr(&whs[buf][f * 72 + u * 8]), whTh + (size_t)f * GN + j0 + u * 8);
        }
        if (t < 16)      cpa16(sptr(&e2t[buf][t * 4]),         e2h  + j0 + t * 4);
        else if (t < 32) cpa16(sptr(&e2bt[buf][(t - 16) * 4]), e2bh + j0 + (t - 16) * 4);
    };

    issue_tile(0);
    cpa_commit();

    const int rt = t >> 1, jh = t & 1;          // phase-1: row / adj-word half
    const float s1i = s1g[h * GN + i0 + rt];
    const float gme = s1i + fdec(gmaxi[h]);
    const float m   = fmaxf(gme, 0.2f * gme);
    const float ci  = ex2f(s1i - m);
    const float ci2 = ex2f(0.2f * s1i - m);

    const int w = t >> 5, ln = t & 31;
    const int r = ln >> 2, c = ln & 3;

    const uint32_t psB = sptr(ps) + (uint32_t)(((w * 16 + (ln & 15)) * 72 +
                                                ((ln >> 4) & 1) * 8) * 2);
    const uint32_t whB0 = sptr(whs[0]) + (uint32_t)((((ln & 7) + ((ln >> 4) & 1) * 8) * 72 +
                                                     ((ln >> 3) & 1) * 8) * 2);
    const uint32_t dnB0 = sptr(whs[0]) + (uint32_t)(((64 + (ln & 7)) * 72 +
                                                     ((ln >> 3) & 1) * 8) * 2);
    const uint32_t bufStride = (uint32_t)(72 * 72 * 2);

    float acc[9][4];
#pragma unroll
    for (int nt = 0; nt < 9; ++nt)
#pragma unroll
        for (int q = 0; q < 4; ++q) acc[nt][q] = 0.f;

    const uint32_t* adjRow = adjbits + (size_t)(i0 + rt) * ADJW;

    for (int tt = 0; tt < NT; ++tt) {
        cpa_wait<0>();           // tile-tt copies done
        __syncthreads();         // block-wide: data visible; phase2(tt-1) done
        if (tt + 1 < NT) { issue_tile(tt + 1); cpa_commit(); }

        const int buf = tt & 1;
        const int j0  = jbase + tt * 64;

        // ---- phase 1: 32 p's (row rt, adj word jh), branch-free max ----
        const uint32_t wv = adjRow[(j0 >> 5) + jh];
        const float2* e2p  = reinterpret_cast<const float2*>(e2t[buf]  + jh * 32);
        const float2* e2bp = reinterpret_cast<const float2*>(e2bt[buf] + jh * 32);
#pragma unroll
        for (int u = 0; u < 4; ++u) {
            uint32_t pk[4];
#pragma unroll
            for (int q = 0; q < 4; ++q) {
                int j = u * 8 + q * 2;
                float2 ev = e2p[u * 4 + q];
                float2 bv = e2bp[u * 4 + q];
                float p0 = fmaxf(ev.x * ci, bv.x * ci2);
                float p1 = fmaxf(ev.y * ci, bv.y * ci2);
                p0 = ((wv >> j) & 1u)       ? p0 : 0.f;
                p1 = ((wv >> (j + 1)) & 1u) ? p1 : 0.f;
                __nv_bfloat162 h2 = __floats2bfloat162_rn(p0, p1);
                pk[q] = *reinterpret_cast<uint32_t*>(&h2);
            }
            *(uint4*)(psW + rt * 36 + jh * 16 + u * 4) =
                make_uint4(pk[0], pk[1], pk[2], pk[3]);
        }
        __syncwarp();            // ps is warp-local: warp-level fence suffices

        // ---- phase 2: warp w -> m-tile w, all 9 n-tiles ----
        const uint32_t whB = whB0 + buf * bufStride;
        const uint32_t dnB = dnB0 + buf * bufStride;
#pragma unroll
        for (int kt = 0; kt < 4; ++kt) {
            uint32_t a[4];
            ldsm4(a, psB + kt * 32);
#pragma unroll
            for (int p = 0; p < 4; ++p) {
                uint32_t b[4];
                ldsm4(b, whB + p * 2304 + kt * 32);
                mma16816(acc[2 * p],     a, b[0], b[1]);
                mma16816(acc[2 * p + 1], a, b[2], b[3]);
            }
            uint32_t d[2];
            ldsm2(d, dnB + kt * 32);
            mma16816(acc[8], a, d[0], d[1]);
        }
    }

    // ---- store partials: slot = h*JS + z ----
    int rA = i0 + w * 16 + r;
    float* pA = part + (((size_t)(h * JS + blockIdx.z)) * GN + rA) * 72;
    float* pB = pA + 8 * 72;
#pragma unroll
    for (int nt = 0; nt < 8; ++nt) {
        int col = nt * 8 + c * 2;
        *(float2*)(pA + col) = make_float2(acc[nt][0], acc[nt][1]);
        *(float2*)(pB + col) = make_float2(acc[nt][2], acc[nt][3]);
    }
    if (c == 0) { pA[64] = acc[8][0]; pB[64] = acc[8][2]; }
}

// ---------------- layer-1 reduce: sum JS1 partials, ELU, bf16 store --------
__global__ void reduce_hbuf_kernel(const float* __restrict__ part,
                                   __nv_bfloat16* __restrict__ outB) {
    int id  = blockIdx.x * 256 + threadIdx.x;
    int row = id >> 8;
    int cp  = (id & 255) * 2;
    int h   = cp >> 6;
    int cl  = cp & 63;
    float n0 = 0.f, n1 = 0.f, d = 0.f;
#pragma unroll
    for (int js = 0; js < JS1; ++js) {
        const float* rp = part + (((size_t)(h * JS1 + js)) * GN + row) * 72;
        float2 nv = *(const float2*)(rp + cl);
        n0 += nv.x; n1 += nv.y; d += rp[64];
    }
    float inv = 1.f / d;
    float v0 = n0 * inv;
    float v1 = n1 * inv;
    v0 = v0 > 0.f ? v0 : (ex2f(v0 * LOG2E) - 1.f);
    v1 = v1 > 0.f ? v1 : (ex2f(v1 * LOG2E) - 1.f);
    *(__nv_bfloat162*)(outB + (size_t)row * FCAT + cp) = __floats2bfloat162_rn(v0, v1);
}

// ---------------- layer-2 reduce: sum JS2 partials + ELU + log_softmax ----
__global__ void reduce_lsm_kernel(const float* __restrict__ part,
                                  float* __restrict__ out) {
    int row = blockIdx.x * 8 + (threadIdx.x >> 5);
    int ln  = threadIdx.x & 31;
    float n0 = 0.f, n1 = 0.f, d = 0.f;
#pragma unroll
    for (int js = 0; js < JS2; ++js) {
        const float* b = part + ((size_t)js * GN + row) * 72;
        n0 += b[ln]; n1 += b[ln + 32]; d += b[64];
    }
    float inv = 1.f / d;
    float v0 = n0 * inv, v1 = n1 * inv;
    v0 = v0 > 0.f ? v0 : (__expf(v0) - 1.f);
    v1 = v1 > 0.f ? v1 : (__expf(v1) - 1.f);
    float mx = fmaxf(v0, v1);
#pragma unroll
    for (int o = 16; o; o >>= 1) mx = fmaxf(mx, __shfl_xor_sync(0xffffffffu, mx, o));
    float s = __expf(v0 - mx) + __expf(v1 - mx);
#pragma unroll
    for (int o = 16; o; o >>= 1) s += __shfl_xor_sync(0xffffffffu, s, o);
    float l = mx + __logf(s);
    out[(size_t)row * 64 + ln]      = v0 - l;
    out[(size_t)row * 64 + ln + 32] = v1 - l;
}

// ---------------- launch ----------------
extern "C" void kernel_launch(void* const* d_in, const int* in_sizes, int n_in,
                              void* d_out, int out_size) {
    const float* x   = (const float*)d_in[0];
    const int*   adj = (const int*)d_in[1];
    const float* W   = (const float*)d_in[2];
    const float* a1  = (const float*)d_in[3];
    const float* a2  = (const float*)d_in[4];
    const float* W2  = (const float*)d_in[5];
    const float* a21 = (const float*)d_in[6];
    const float* a22 = (const float*)d_in[7];
    float* out = (float*)d_out;

    uint32_t* adjbits; unsigned* gmaxi;
    float *wh1, *s1, *s2, *e2, *e2b, *wh2, *s21, *s22, *e22, *e22b, *part;
    __nv_bfloat16 *xb, *Wb, *W2b, *whTb, *hbufb, *whT2b;
    cudaGetSymbolAddress((void**)&adjbits, g_adjbits);
    cudaGetSymbolAddress((void**)&gmaxi, g_gmaxi);
    cudaGetSymbolAddress((void**)&xb,    g_xb);
    cudaGetSymbolAddress((void**)&Wb,    g_Wb);
    cudaGetSymbolAddress((void**)&W2b,   g_W2b);
    cudaGetSymbolAddress((void**)&wh1,   g_wh1);
    cudaGetSymbolAddress((void**)&whTb,  g_whTb);
    cudaGetSymbolAddress((void**)&s1,    g_s1);
    cudaGetSymbolAddress((void**)&s2,    g_s2);
    cudaGetSymbolAddress((void**)&e2,    g_e2);
    cudaGetSymbolAddress((void**)&e2b,   g_e2b);
    cudaGetSymbolAddress((void**)&hbufb, g_hbufb);
    cudaGetSymbolAddress((void**)&wh2,   g_wh2);
    cudaGetSymbolAddress((void**)&whT2b, g_whT2b);
    cudaGetSymbolAddress((void**)&s21,   g_s21);
    cudaGetSymbolAddress((void**)&s22,   g_s22);
    cudaGetSymbolAddress((void**)&e22,   g_e22);
    cudaGetSymbolAddress((void**)&e22b,  g_e22b);
    cudaGetSymbolAddress((void**)&part,  g_part);

    pack_adj_kernel<<<(GN * GN) / 1024, 256>>>(adj, adjbits, gmaxi);
    cvt_all_kernel<<<(GN * FCAT + FCAT * FCAT + HIDF * FCAT) / 512, 256>>>(
        x, xb, W, Wb, W2, W2b);
    gemm_bf16_nt<<<dim3(FCAT / 64, GN / 128), 256>>>(xb, Wb, wh1, FCAT, FCAT);
    scores1_kernel<<<GN / 8, 256>>>(wh1, a1, a2, s1, s2, e2, e2b, gmaxi);
    transpose_cvt_kernel<<<dim3(FCAT / 32, GN / 32), dim3(32, 8)>>>(wh1, whTb, FCAT);
    attn_mma_kernel<JS1><<<dim3(GN / 128, GH, JS1), 256>>>(whTb, s1, e2, e2b,
                                                           gmaxi, adjbits, part);
    reduce_hbuf_kernel<<<GN, 256>>>(part, hbufb);
    gemm_bf16_nt<<<dim3(1, GN / 128), 256>>>(hbufb, W2b, wh2, FCAT, HIDF);
    scores_kernel<<<GN / 8, 256>>>(wh2, HIDF, 1, a21, a22, s21, s22, e22, e22b,
                                   gmaxi + 8);
    transpose_cvt_kernel<<<dim3(HIDF / 32, GN / 32), dim3(32, 8)>>>(wh2, whT2b, HIDF);
    attn_mma_kernel<JS2><<<dim3(GN / 128, 1, JS2), 256>>>(whT2b, s21, e22, e22b,
                                                          gmaxi + 8, adjbits, part);
    reduce_lsm_kernel<<<GN / 8, 256>>>(part, out);
}